// round 1
// baseline (speedup 1.0000x reference)
#include <cuda_runtime.h>

// ---------------------------------------------------------------------------
// Problem dims
// ---------------------------------------------------------------------------
constexpr int BATCH = 128;
// conv1: (128,3,224,224) -> (128,32,55,55), k=8, s=4
constexpr int C1 = 3,  H1 = 224, W1 = 224, KK1 = 8, S1 = 4, OC1 = 32, OH1 = 55, OW1 = 55;
// conv2: (128,32,55,55) -> (128,64,26,26), k=4, s=2
constexpr int C2 = 32, H2 = 55,  W2 = 55,  KK2 = 4, S2 = 2, OC2 = 64, OH2 = 26, OW2 = 26;
// conv3: (128,64,26,26) -> (128,64,24,24), k=3, s=1
constexpr int C3 = 64, H3 = 26,  W3 = 26,  KK3 = 3, S3 = 1, OC3 = 64, OH3 = 24, OW3 = 24;

constexpr int F3K   = OC3 * OH3 * OW3;   // 36864
constexpr int FCK   = F3K + 90;          // 36954
constexpr int KSPLIT = 37;               // 36 chunks of 1024 cover f3, chunk 36 = history(90)

// ---------------------------------------------------------------------------
// Device scratch (no allocation allowed -> __device__ globals)
// ---------------------------------------------------------------------------
__device__ float g_f1[BATCH * OC1 * OH1 * OW1];     // ~49.6 MB
__device__ float g_f2[BATCH * OC2 * OH2 * OW2];     // ~22.2 MB
__device__ float g_f3[BATCH * OC3 * OH3 * OW3];     // ~18.9 MB
__device__ float g_h1p[KSPLIT * BATCH * 128];       // split-K partials, ~2.4 MB

// ---------------------------------------------------------------------------
// Direct conv: each thread computes OCB=8 output channels x 2 spatial points.
// Weights for the 8-channel group live in smem (warp-broadcast reads).
// ---------------------------------------------------------------------------
template <int C, int H, int W, int K, int S, int OH, int OW, int OCB, int OC>
__global__ void conv_kernel(const float* __restrict__ in,
                            const float* __restrict__ wgt,
                            const float* __restrict__ bias,
                            float* __restrict__ out)
{
    constexpr int CKK  = C * K * K;
    constexpr int TOT  = OH * OW;
    constexpr int HALF = (TOT + 1) / 2;

    __shared__ float ws[OCB * CKK];

    const int b   = blockIdx.z;
    const int ocg = blockIdx.y;

    for (int idx = threadIdx.x; idx < OCB * CKK; idx += blockDim.x) {
        int o = idx / CKK, r = idx % CKK;
        ws[idx] = wgt[(ocg * OCB + o) * CKK + r];
    }
    __syncthreads();

    const int t = blockIdx.x * blockDim.x + threadIdx.x;
    if (t >= HALF) return;

    const int sp0 = t;
    const int sp1 = t + HALF;
    const bool v1 = (sp1 < TOT);

    const int oh0 = sp0 / OW, ow0 = sp0 % OW;
    const int oh1 = v1 ? sp1 / OW : 0;
    const int ow1 = v1 ? sp1 % OW : 0;

    const float* in0 = in + ((b * C) * H + oh0 * S) * W + ow0 * S;
    const float* in1 = in + ((b * C) * H + oh1 * S) * W + ow1 * S;

    float acc0[OCB], acc1[OCB];
#pragma unroll
    for (int o = 0; o < OCB; o++) { acc0[o] = 0.f; acc1[o] = 0.f; }

    for (int c = 0; c < C; c++) {
#pragma unroll
        for (int kh = 0; kh < K; kh++) {
#pragma unroll
            for (int kw = 0; kw < K; kw++) {
                const int ioff = (c * H + kh) * W + kw;
                const float v0 = in0[ioff];
                const float u1 = v1 ? in1[ioff] : 0.f;
                const float* wp = ws + c * K * K + kh * K + kw;
#pragma unroll
                for (int o = 0; o < OCB; o++) {
                    const float wv = wp[o * CKK];
                    acc0[o] += v0 * wv;
                    acc1[o] += u1 * wv;
                }
            }
        }
    }

#pragma unroll
    for (int o = 0; o < OCB; o++) {
        const int oc = ocg * OCB + o;
        const float bv = bias[oc];
        out[((b * OC + oc) * OH + oh0) * OW + ow0] = fmaxf(acc0[o] + bv, 0.f);
        if (v1)
            out[((b * OC + oc) * OH + oh1) * OW + ow1] = fmaxf(acc1[o] + bv, 0.f);
    }
}

// ---------------------------------------------------------------------------
// fc1: h1[b,j] = sum_k x[b,k] * w1[j,k]   (x = [conv3 flat | history])
// Split-K GEMM: grid (2,2,37) = 148 blocks (one wave). Deterministic:
// each block writes its own partial tile into g_h1p (no atomics).
// ---------------------------------------------------------------------------
__global__ void fc1_kernel(const float* __restrict__ hist,
                           const float* __restrict__ w1)
{
    __shared__ float As[32 * 65];
    __shared__ float Bs[32 * 65];

    const int m0  = blockIdx.y * 64;       // batch rows
    const int n0  = blockIdx.x * 64;       // output features
    const int bz  = blockIdx.z;
    const int kc0 = bz * 1024;
    const int kend = min(1024, FCK - kc0); // 1024 or 90 (last chunk)

    const int tid = threadIdx.x;
    const int ty = tid >> 4, tx = tid & 15;

    float acc[4][4] = {};

    for (int kt = 0; kt * 32 < kend; kt++) {
#pragma unroll
        for (int l = 0; l < 8; l++) {
            const int idx = tid + l * 256;
            const int row = idx >> 5, kk = idx & 31;
            const int k = kc0 + kt * 32 + kk;
            float av = 0.f, bv = 0.f;
            if (k < FCK) {
                av = (k < F3K) ? g_f3[(m0 + row) * F3K + k]
                               : hist[(m0 + row) * 90 + (k - F3K)];
                bv = w1[(n0 + row) * FCK + k];
            }
            As[kk * 65 + row] = av;
            Bs[kk * 65 + row] = bv;
        }
        __syncthreads();

#pragma unroll
        for (int kk = 0; kk < 32; kk++) {
            float a[4], bb[4];
#pragma unroll
            for (int i = 0; i < 4; i++) a[i]  = As[kk * 65 + ty * 4 + i];
#pragma unroll
            for (int j = 0; j < 4; j++) bb[j] = Bs[kk * 65 + tx * 4 + j];
#pragma unroll
            for (int i = 0; i < 4; i++)
#pragma unroll
                for (int j = 0; j < 4; j++)
                    acc[i][j] += a[i] * bb[j];
        }
        __syncthreads();
    }

    float* dst = g_h1p + bz * (BATCH * 128);
#pragma unroll
    for (int i = 0; i < 4; i++)
#pragma unroll
        for (int j = 0; j < 4; j++)
            dst[(m0 + ty * 4 + i) * 128 + (n0 + tx * 4 + j)] = acc[i][j];
}

// ---------------------------------------------------------------------------
// LIF recurrence: T=10 steps, h1 constant per step. One block per batch row.
// w2 (256x128) staged in smem with +1 padding -> conflict-free row reads.
// ---------------------------------------------------------------------------
__global__ void lif_kernel(const float* __restrict__ b1,
                           const float* __restrict__ w2,
                           const float* __restrict__ b2,
                           const float* __restrict__ w3,
                           const float* __restrict__ b3,
                           float* __restrict__ out)
{
    extern __shared__ float sm[];
    float* w2s  = sm;                 // 256*129
    float* w3s  = w2s + 256 * 129;    // 9*256
    float* spk1 = w3s + 9 * 256;      // 128
    float* spk2 = spk1 + 128;         // 256

    const int b   = blockIdx.x;
    const int tid = threadIdx.x;

    for (int idx = tid; idx < 256 * 128; idx += blockDim.x) {
        const int j = idx >> 7, i = idx & 127;
        w2s[j * 129 + i] = w2[idx];
    }
    for (int idx = tid; idx < 9 * 256; idx += blockDim.x) w3s[idx] = w3[idx];
    __syncthreads();

    float h1v = 0.f, mem1 = 0.f, syn1 = 0.f;
    if (tid < 128) {
        h1v = b1[tid];
        for (int p = 0; p < KSPLIT; p++)      // fixed-order split-K reduction
            h1v += g_h1p[p * (BATCH * 128) + b * 128 + tid];
    }
    float b2v = 0.f, mem2 = 0.f, syn2 = 0.f;
    if (tid < 256) b2v = b2[tid];

    const int w = tid >> 5, lane = tid & 31;
    float b3v = 0.f, mem3 = 0.f, syn3 = 0.f, pot = 0.f;
    if (w < 9 && lane == 0) b3v = b3[w];

    for (int t = 0; t < 10; t++) {
        if (tid < 128) {
            syn1 = 0.9f * syn1 + h1v;
            mem1 = 0.8f * mem1 + syn1;
            const float s = (mem1 > 1.f) ? 1.f : 0.f;
            mem1 -= s;
            spk1[tid] = s;
        }
        __syncthreads();
        if (tid < 256) {
            float h2 = b2v;
#pragma unroll 8
            for (int i = 0; i < 128; i++) h2 += spk1[i] * w2s[tid * 129 + i];
            syn2 = 0.9f * syn2 + h2;
            mem2 = 0.8f * mem2 + syn2;
            const float s = (mem2 > 1.f) ? 1.f : 0.f;
            mem2 -= s;
            spk2[tid] = s;
        }
        __syncthreads();
        if (w < 9) {
            float part = 0.f;
#pragma unroll
            for (int i = 0; i < 8; i++)
                part += spk2[lane + i * 32] * w3s[w * 256 + lane + i * 32];
#pragma unroll
            for (int o = 16; o > 0; o >>= 1)
                part += __shfl_xor_sync(0xffffffff, part, o);
            if (lane == 0) {
                syn3 = 0.9f * syn3 + (part + b3v);
                mem3 = 0.8f * mem3 + syn3;
                pot += mem3;
            }
        }
        // spk2 readers (stage 3) are separated from next step's spk2 writers
        // (stage 2) by the stage-1 __syncthreads of the next iteration.
    }

    if (w < 9 && lane == 0) out[b * 9 + w] = pot * 0.1f;
}

// ---------------------------------------------------------------------------
// Launch
// ---------------------------------------------------------------------------
extern "C" void kernel_launch(void* const* d_in, const int* in_sizes, int n_in,
                              void* d_out, int out_size)
{
    const float* state = (const float*)d_in[0];
    const float* hist  = (const float*)d_in[1];
    const float* cw1   = (const float*)d_in[2];
    const float* cb1   = (const float*)d_in[3];
    const float* cw2   = (const float*)d_in[4];
    const float* cb2   = (const float*)d_in[5];
    const float* cw3   = (const float*)d_in[6];
    const float* cb3   = (const float*)d_in[7];
    const float* w1    = (const float*)d_in[8];
    const float* b1    = (const float*)d_in[9];
    const float* w2    = (const float*)d_in[10];
    const float* b2    = (const float*)d_in[11];
    const float* w3    = (const float*)d_in[12];
    const float* b3    = (const float*)d_in[13];
    float* out = (float*)d_out;

    float* f1; cudaGetSymbolAddress((void**)&f1, g_f1);
    float* f2; cudaGetSymbolAddress((void**)&f2, g_f2);
    float* f3; cudaGetSymbolAddress((void**)&f3, g_f3);

    // conv1: HALF = 1513 -> 12 blocks of 128; oc groups = 4
    conv_kernel<C1, H1, W1, KK1, S1, OH1, OW1, 8, OC1>
        <<<dim3(12, OC1 / 8, BATCH), 128>>>(state, cw1, cb1, f1);
    // conv2: HALF = 338 -> 3 blocks; oc groups = 8
    conv_kernel<C2, H2, W2, KK2, S2, OH2, OW2, 8, OC2>
        <<<dim3(3, OC2 / 8, BATCH), 128>>>(f1, cw2, cb2, f2);
    // conv3: HALF = 288 -> 3 blocks; oc groups = 8
    conv_kernel<C3, H3, W3, KK3, S3, OH3, OW3, 8, OC3>
        <<<dim3(3, OC3 / 8, BATCH), 128>>>(f2, cw3, cb3, f3);

    // fc1 split-K GEMM: 2x2 tiles x 37 K-chunks = 148 blocks
    fc1_kernel<<<dim3(2, 2, KSPLIT), 256>>>(hist, w1);

    // LIF recurrence, one block per batch row
    const int lif_smem = (256 * 129 + 9 * 256 + 128 + 256) * (int)sizeof(float);
    cudaFuncSetAttribute(lif_kernel, cudaFuncAttributeMaxDynamicSharedMemorySize,
                         lif_smem);
    lif_kernel<<<BATCH, 320, lif_smem>>>(b1, w2, b2, w3, b3, out);
}

// round 2
// speedup vs baseline: 1.0139x; 1.0139x over previous
#include <cuda_runtime.h>

// ---------------------------------------------------------------------------
// Problem dims
// ---------------------------------------------------------------------------
constexpr int BATCH = 128;
constexpr int C1 = 3,  H1 = 224, W1 = 224, KK1 = 8, S1 = 4, OC1 = 32, OH1 = 55, OW1 = 55;
constexpr int C2 = 32, H2 = 55,  W2 = 55,  KK2 = 4, S2 = 2, OC2 = 64, OH2 = 26, OW2 = 26;
constexpr int C3 = 64, H3 = 26,  W3 = 26,  KK3 = 3, S3 = 1, OC3 = 64, OH3 = 24, OW3 = 24;

constexpr int F3K    = OC3 * OH3 * OW3;   // 36864
constexpr int FCK    = F3K + 90;          // 36954
constexpr int KCHUNK = 256;
constexpr int NCHUNK = F3K / KCHUNK + 1;  // 144 data chunks + 1 history chunk = 145

// ---------------------------------------------------------------------------
// Device scratch
// ---------------------------------------------------------------------------
__device__ float g_f1[BATCH * OC1 * OH1 * OW1];
__device__ float g_f2[BATCH * OC2 * OH2 * OW2];
__device__ float g_f3[BATCH * OC3 * OH3 * OW3];
__device__ float g_h1p[NCHUNK * BATCH * 128];

// ---------------------------------------------------------------------------
// Packed fp32x2 helpers (sm_103a FFMA2 — double-rate packed fp32 FMA)
// ---------------------------------------------------------------------------
typedef unsigned long long u64;

__device__ __forceinline__ u64 pack2(float lo, float hi) {
    u64 r;
    asm("mov.b64 %0, {%1, %2};" : "=l"(r) : "f"(lo), "f"(hi));
    return r;
}
__device__ __forceinline__ void unpack2(u64 v, float& lo, float& hi) {
    asm("mov.b64 {%0, %1}, %2;" : "=f"(lo), "=f"(hi) : "l"(v));
}
__device__ __forceinline__ void ffma2(u64& d, u64 a, u64 b) {
    asm("fma.rn.f32x2 %0, %1, %2, %0;" : "+l"(d) : "l"(a), "l"(b));
}

// ---------------------------------------------------------------------------
// Direct conv: 4 spatial positions (2 f32x2 pairs) x OCB=8 output channels
// per thread. Weights duplicated {w,w} in smem -> one LDS.64 per FFMA2 pair.
// ---------------------------------------------------------------------------
template <int C, int H, int W, int K, int S, int OH, int OW, int OCB, int OC>
__global__ void conv_kernel(const float* __restrict__ in,
                            const float* __restrict__ wgt,
                            const float* __restrict__ bias,
                            float* __restrict__ out)
{
    constexpr int CKK = C * K * K;
    constexpr int TOT = OH * OW;
    constexpr int QTR = (TOT + 3) / 4;

    __shared__ float2 ws[OCB * CKK];

    const int b   = blockIdx.z;
    const int ocg = blockIdx.y;

    for (int idx = threadIdx.x; idx < OCB * CKK; idx += blockDim.x) {
        const int o = idx / CKK, r = idx % CKK;
        const float w = wgt[(ocg * OCB + o) * CKK + r];
        ws[idx] = make_float2(w, w);
    }
    __syncthreads();

    const int t = blockIdx.x * blockDim.x + threadIdx.x;
    if (t >= QTR) return;

    int  sp[4];
    bool val[4];
    const float* inp[4];
#pragma unroll
    for (int p = 0; p < 4; p++) {
        int s = t + p * QTR;
        val[p] = (s < TOT);
        if (s >= TOT) s = TOT - 1;
        sp[p] = s;
        const int oh = s / OW, ow = s % OW;
        inp[p] = in + ((b * C) * H + oh * S) * W + ow * S;
    }

    u64 acc01[OCB], acc23[OCB];
#pragma unroll
    for (int o = 0; o < OCB; o++) { acc01[o] = 0ull; acc23[o] = 0ull; }

    for (int c = 0; c < C; c++) {
#pragma unroll
        for (int kh = 0; kh < K; kh++) {
#pragma unroll
            for (int kw = 0; kw < K; kw++) {
                const int ioff = (c * H + kh) * W + kw;
                const float v0 = inp[0][ioff];
                const float v1 = val[1] ? inp[1][ioff] : 0.f;
                const float v2 = val[2] ? inp[2][ioff] : 0.f;
                const float v3 = val[3] ? inp[3][ioff] : 0.f;
                const u64 v01 = pack2(v0, v1);
                const u64 v23 = pack2(v2, v3);
                const float2* wp = ws + c * K * K + kh * K + kw;
#pragma unroll
                for (int o = 0; o < OCB; o++) {
                    const u64 ww = *reinterpret_cast<const u64*>(&wp[o * CKK]);
                    ffma2(acc01[o], v01, ww);
                    ffma2(acc23[o], v23, ww);
                }
            }
        }
    }

#pragma unroll
    for (int o = 0; o < OCB; o++) {
        const int oc = ocg * OCB + o;
        const float bv = bias[oc];
        float a0, a1, a2, a3;
        unpack2(acc01[o], a0, a1);
        unpack2(acc23[o], a2, a3);
        float* op = out + ((b * OC + oc) * OH) * OW;
        op[sp[0]] = fmaxf(a0 + bv, 0.f);
        if (val[1]) op[sp[1]] = fmaxf(a1 + bv, 0.f);
        if (val[2]) op[sp[2]] = fmaxf(a2 + bv, 0.f);
        if (val[3]) op[sp[3]] = fmaxf(a3 + bv, 0.f);
    }
}

// ---------------------------------------------------------------------------
// fc1 split-K GEMM: h1[b,j] = sum_k x[b,k] * w1[j,k]
// grid (2,2,145) = 580 blocks (~4/SM). Vectorized loads, no atomics.
// ---------------------------------------------------------------------------
__global__ void fc1_kernel(const float* __restrict__ hist,
                           const float* __restrict__ w1)
{
    __shared__ float As[32 * 68];
    __shared__ float Bs[32 * 68];

    const int m0  = blockIdx.y * 64;   // batch rows
    const int n0  = blockIdx.x * 64;   // output features
    const int bz  = blockIdx.z;
    const int tid = threadIdx.x;
    const int ty = tid >> 4, tx = tid & 15;

    float acc[4][4] = {};

    if (bz < NCHUNK - 1) {
        const int kc0 = bz * KCHUNK;
#pragma unroll 1
        for (int kt = 0; kt < KCHUNK; kt += 32) {
            const int kb = kc0 + kt;
            // A (g_f3): 64 rows x 32 k -> 512 float4, 2 per thread
#pragma unroll
            for (int l = 0; l < 2; l++) {
                const int idx = tid + l * 256;
                const int row = idx >> 3, kq = idx & 7;
                const float4 v = *reinterpret_cast<const float4*>(
                    g_f3 + (m0 + row) * F3K + kb + kq * 4);
                As[(kq * 4 + 0) * 68 + row] = v.x;
                As[(kq * 4 + 1) * 68 + row] = v.y;
                As[(kq * 4 + 2) * 68 + row] = v.z;
                As[(kq * 4 + 3) * 68 + row] = v.w;
            }
            // B (w1): row stride 36954 -> only 8B aligned -> float2
#pragma unroll
            for (int l = 0; l < 4; l++) {
                const int idx = tid + l * 256;
                const int row = idx >> 4, kd = idx & 15;
                const float2 v = *reinterpret_cast<const float2*>(
                    w1 + (n0 + row) * FCK + kb + kd * 2);
                Bs[(kd * 2 + 0) * 68 + row] = v.x;
                Bs[(kd * 2 + 1) * 68 + row] = v.y;
            }
            __syncthreads();
#pragma unroll
            for (int kk = 0; kk < 32; kk++) {
                const float4 a4 = *reinterpret_cast<const float4*>(&As[kk * 68 + ty * 4]);
                const float4 b4 = *reinterpret_cast<const float4*>(&Bs[kk * 68 + tx * 4]);
                const float a[4] = {a4.x, a4.y, a4.z, a4.w};
                const float bb[4] = {b4.x, b4.y, b4.z, b4.w};
#pragma unroll
                for (int i = 0; i < 4; i++)
#pragma unroll
                    for (int j = 0; j < 4; j++)
                        acc[i][j] += a[i] * bb[j];
            }
            __syncthreads();
        }
    } else {
        // history chunk: k in [F3K, F3K+90), scalar guarded loads
#pragma unroll 1
        for (int kt = 0; kt < 96; kt += 32) {
#pragma unroll
            for (int l = 0; l < 8; l++) {
                const int idx = tid + l * 256;
                const int row = idx >> 5, kk = idx & 31;
                const int k = kt + kk;
                float av = 0.f, bv = 0.f;
                if (k < 90) {
                    av = hist[(m0 + row) * 90 + k];
                    bv = w1[(n0 + row) * FCK + F3K + k];
                }
                As[kk * 68 + row] = av;
                Bs[kk * 68 + row] = bv;
            }
            __syncthreads();
#pragma unroll
            for (int kk = 0; kk < 32; kk++) {
                const float4 a4 = *reinterpret_cast<const float4*>(&As[kk * 68 + ty * 4]);
                const float4 b4 = *reinterpret_cast<const float4*>(&Bs[kk * 68 + tx * 4]);
                const float a[4] = {a4.x, a4.y, a4.z, a4.w};
                const float bb[4] = {b4.x, b4.y, b4.z, b4.w};
#pragma unroll
                for (int i = 0; i < 4; i++)
#pragma unroll
                    for (int j = 0; j < 4; j++)
                        acc[i][j] += a[i] * bb[j];
            }
            __syncthreads();
        }
    }

    float* dst = g_h1p + bz * (BATCH * 128);
#pragma unroll
    for (int i = 0; i < 4; i++)
#pragma unroll
        for (int j = 0; j < 4; j++)
            dst[(m0 + ty * 4 + i) * 128 + (n0 + tx * 4 + j)] = acc[i][j];
}

// ---------------------------------------------------------------------------
// LIF recurrence: T=10 steps, h1 constant per step. One block per batch row.
// ---------------------------------------------------------------------------
__global__ void lif_kernel(const float* __restrict__ b1,
                           const float* __restrict__ w2,
                           const float* __restrict__ b2,
                           const float* __restrict__ w3,
                           const float* __restrict__ b3,
                           float* __restrict__ out)
{
    extern __shared__ float sm[];
    float* w2s  = sm;                 // 256*129
    float* w3s  = w2s + 256 * 129;    // 9*256
    float* spk1 = w3s + 9 * 256;      // 128
    float* spk2 = spk1 + 128;         // 256

    const int b   = blockIdx.x;
    const int tid = threadIdx.x;

    for (int idx = tid; idx < 256 * 128; idx += blockDim.x) {
        const int j = idx >> 7, i = idx & 127;
        w2s[j * 129 + i] = w2[idx];
    }
    for (int idx = tid; idx < 9 * 256; idx += blockDim.x) w3s[idx] = w3[idx];
    __syncthreads();

    float h1v = 0.f, mem1 = 0.f, syn1 = 0.f;
    if (tid < 128) {
        h1v = b1[tid];
        for (int p = 0; p < NCHUNK; p++)   // fixed-order split-K reduction
            h1v += g_h1p[p * (BATCH * 128) + b * 128 + tid];
    }
    float b2v = 0.f, mem2 = 0.f, syn2 = 0.f;
    if (tid < 256) b2v = b2[tid];

    const int w = tid >> 5, lane = tid & 31;
    float b3v = 0.f, mem3 = 0.f, syn3 = 0.f, pot = 0.f;
    if (w < 9 && lane == 0) b3v = b3[w];

    for (int t = 0; t < 10; t++) {
        if (tid < 128) {
            syn1 = 0.9f * syn1 + h1v;
            mem1 = 0.8f * mem1 + syn1;
            const float s = (mem1 > 1.f) ? 1.f : 0.f;
            mem1 -= s;
            spk1[tid] = s;
        }
        __syncthreads();
        if (tid < 256) {
            float h2 = b2v;
#pragma unroll 8
            for (int i = 0; i < 128; i++) h2 += spk1[i] * w2s[tid * 129 + i];
            syn2 = 0.9f * syn2 + h2;
            mem2 = 0.8f * mem2 + syn2;
            const float s = (mem2 > 1.f) ? 1.f : 0.f;
            mem2 -= s;
            spk2[tid] = s;
        }
        __syncthreads();
        if (w < 9) {
            float part = 0.f;
#pragma unroll
            for (int i = 0; i < 8; i++)
                part += spk2[lane + i * 32] * w3s[w * 256 + lane + i * 32];
#pragma unroll
            for (int o = 16; o > 0; o >>= 1)
                part += __shfl_xor_sync(0xffffffff, part, o);
            if (lane == 0) {
                syn3 = 0.9f * syn3 + (part + b3v);
                mem3 = 0.8f * mem3 + syn3;
                pot += mem3;
            }
        }
    }

    if (w < 9 && lane == 0) out[b * 9 + w] = pot * 0.1f;
}

// ---------------------------------------------------------------------------
// Launch
// ---------------------------------------------------------------------------
extern "C" void kernel_launch(void* const* d_in, const int* in_sizes, int n_in,
                              void* d_out, int out_size)
{
    const float* state = (const float*)d_in[0];
    const float* hist  = (const float*)d_in[1];
    const float* cw1   = (const float*)d_in[2];
    const float* cb1   = (const float*)d_in[3];
    const float* cw2   = (const float*)d_in[4];
    const float* cb2   = (const float*)d_in[5];
    const float* cw3   = (const float*)d_in[6];
    const float* cb3   = (const float*)d_in[7];
    const float* w1    = (const float*)d_in[8];
    const float* b1    = (const float*)d_in[9];
    const float* w2    = (const float*)d_in[10];
    const float* b2    = (const float*)d_in[11];
    const float* w3    = (const float*)d_in[12];
    const float* b3    = (const float*)d_in[13];
    float* out = (float*)d_out;

    float* f1; cudaGetSymbolAddress((void**)&f1, g_f1);
    float* f2; cudaGetSymbolAddress((void**)&f2, g_f2);
    float* f3; cudaGetSymbolAddress((void**)&f3, g_f3);

    // conv1: TOT=3025, QTR=757 -> 6 blocks of 128; 4 oc-groups
    conv_kernel<C1, H1, W1, KK1, S1, OH1, OW1, 8, OC1>
        <<<dim3(6, OC1 / 8, BATCH), 128>>>(state, cw1, cb1, f1);
    // conv2: TOT=676, QTR=169 -> 2 blocks; 8 oc-groups
    conv_kernel<C2, H2, W2, KK2, S2, OH2, OW2, 8, OC2>
        <<<dim3(2, OC2 / 8, BATCH), 128>>>(f1, cw2, cb2, f2);
    // conv3: TOT=576, QTR=144 -> 2 blocks; 8 oc-groups
    conv_kernel<C3, H3, W3, KK3, S3, OH3, OW3, 8, OC3>
        <<<dim3(2, OC3 / 8, BATCH), 128>>>(f2, cw3, cb3, f3);

    // fc1 split-K GEMM: 2x2 output tiles x 145 K-chunks = 580 blocks
    fc1_kernel<<<dim3(2, 2, NCHUNK), 256>>>(hist, w1);

    // LIF recurrence, one block per batch row
    const int lif_smem = (256 * 129 + 9 * 256 + 128 + 256) * (int)sizeof(float);
    cudaFuncSetAttribute(lif_kernel, cudaFuncAttributeMaxDynamicSharedMemorySize,
                         lif_smem);
    lif_kernel<<<BATCH, 320, lif_smem>>>(b1, w2, b2, w3, b3, out);
}

// round 3
// speedup vs baseline: 1.1003x; 1.0852x over previous
#include <cuda_runtime.h>

// ---------------------------------------------------------------------------
// Problem dims
// ---------------------------------------------------------------------------
constexpr int BATCH = 128;
constexpr int C1 = 3,  H1 = 224, W1 = 224, KK1 = 8, S1 = 4, OC1 = 32, OH1 = 55, OW1 = 55;
constexpr int C2 = 32, H2 = 55,  W2 = 55,  KK2 = 4, S2 = 2, OC2 = 64, OH2 = 26, OW2 = 26;
constexpr int C3 = 64, H3 = 26,  W3 = 26,  KK3 = 3, S3 = 1, OC3 = 64, OH3 = 24, OW3 = 24;

constexpr int F3K    = OC3 * OH3 * OW3;   // 36864
constexpr int FCK    = F3K + 90;          // 36954
constexpr int KCHUNK = 256;
constexpr int NCHUNK = F3K / KCHUNK + 1;  // 145

// ---------------------------------------------------------------------------
// Device scratch
// ---------------------------------------------------------------------------
__device__ float g_f1[BATCH * OC1 * OH1 * OW1];
__device__ float g_f2[BATCH * OC2 * OH2 * OW2];
__device__ float g_f3[BATCH * OC3 * OH3 * OW3];
__device__ float g_h1p[NCHUNK * BATCH * 128];
__device__ float g_wt1[KK1 * KK1 * C1 * OC1];   // 192*32
__device__ float g_wt2[KK2 * KK2 * C2 * OC2];   // 512*64
__device__ float g_wt3[KK3 * KK3 * C3 * OC3];   // 576*64

typedef unsigned long long u64;

__device__ __forceinline__ void unpack2(u64 v, float& lo, float& hi) {
    asm("mov.b64 {%0, %1}, %2;" : "=f"(lo), "=f"(hi) : "l"(v));
}
__device__ __forceinline__ void ffma2(u64& d, u64 a, u64 b) {
    asm("fma.rn.f32x2 %0, %1, %2, %0;" : "+l"(d) : "l"(a), "l"(b));
}

// ---------------------------------------------------------------------------
// Weight transpose: wT[k][oc] = w[oc][k]  (tiny)
// ---------------------------------------------------------------------------
__global__ void transpose_w(const float* __restrict__ w, float* __restrict__ wT,
                            int OC, int CKK)
{
    const int i = blockIdx.x * 256 + threadIdx.x;
    if (i < OC * CKK) {
        const int oc = i / CKK, k = i % CKK;
        wT[k * OC + oc] = w[i];
    }
}

// ---------------------------------------------------------------------------
// Implicit-GEMM conv: C[P, OC] = patch[P, CKK] x wT[CKK, OC]
// Per thread: 8 positions x 4 ocs (2 oc-pairs) -> 16 FFMA2 per k-step.
// Patches staged in smem pre-duplicated {v,v}; weights natively paired.
// ---------------------------------------------------------------------------
template <int C, int H, int W, int K, int S, int OH, int OW, int OC,
          int TX, int TY, int NT>
__global__ void __launch_bounds__(TX * TY, 3)
conv_gemm(const float* __restrict__ in, const float* __restrict__ wT,
          const float* __restrict__ bias, float* __restrict__ out)
{
    constexpr int KSQ = K * K, CKK = C * KSQ, TOT = OH * OW;
    constexpr int PT = TY * 8;
    constexpr int THREADS = TX * TY;
    constexpr int PSTRIDE = PT + 2;   // float2 units (keeps 16B alignment)
    constexpr int WSTRIDE = OC + 4;   // floats (16B-aligned rows)

    __shared__ float2 Ps2[16 * PSTRIDE];
    __shared__ float  Ws[16 * WSTRIDE];

    const int tid = threadIdx.x;
    const int tx = tid / TY, ty = tid % TY;

    float bq[4];
#pragma unroll
    for (int j = 0; j < 4; j++) bq[j] = bias[tx * 4 + j];

    const int tile_total = BATCH * NT;
    for (int bt = blockIdx.x; bt < tile_total; bt += gridDim.x) {
        const int b = bt / NT, tile = bt % NT;
        const int p0 = tile * PT;

        u64 acc[8][2];
#pragma unroll
        for (int p = 0; p < 8; p++) { acc[p][0] = 0ull; acc[p][1] = 0ull; }

        for (int kc = 0; kc < CKK; kc += 16) {
            __syncthreads();
            // stage weights: 16 x OC
#pragma unroll
            for (int l = 0; l < (16 * OC) / THREADS; l++) {
                const int e = tid + l * THREADS;
                const int kk = e / OC, oc = e % OC;
                Ws[kk * WSTRIDE + oc] = wT[(kc + kk) * OC + oc];
            }
            // stage patches (duplicated pairs): 16 x PT
#pragma unroll
            for (int l = 0; l < (16 * PT) / THREADS; l++) {
                const int e = tid + l * THREADS;
                const int kk = e / PT, p = e % PT;
                const int k = kc + kk;
                const int c = k / KSQ, r = k % KSQ;
                const int kh = r / K, kw = r % K;
                int pp = p0 + p;
                if (pp >= TOT) pp = TOT - 1;
                const int oh = pp / OW, ow = pp % OW;
                const float v = in[((b * C + c) * H + oh * S + kh) * W + ow * S + kw];
                Ps2[kk * PSTRIDE + p] = make_float2(v, v);
            }
            __syncthreads();
            // compute
#pragma unroll
            for (int kk = 0; kk < 16; kk++) {
                const u64* wp = reinterpret_cast<const u64*>(&Ws[kk * WSTRIDE + tx * 4]);
                const u64 b01 = wp[0];
                const u64 b23 = wp[1];
#pragma unroll
                for (int p = 0; p < 8; p++) {
                    const u64 av = *reinterpret_cast<const u64*>(
                        &Ps2[kk * PSTRIDE + ty + p * TY]);
                    ffma2(acc[p][0], av, b01);
                    ffma2(acc[p][1], av, b23);
                }
            }
        }
        // epilogue: bias + ReLU, coalesced along ty
#pragma unroll
        for (int p = 0; p < 8; p++) {
            const int pp = p0 + ty + p * TY;
            if (pp < TOT) {
                float a0, a1, a2, a3;
                unpack2(acc[p][0], a0, a1);
                unpack2(acc[p][1], a2, a3);
                float* op = out + (b * OC + tx * 4) * TOT + pp;
                op[0 * TOT] = fmaxf(a0 + bq[0], 0.f);
                op[1 * TOT] = fmaxf(a1 + bq[1], 0.f);
                op[2 * TOT] = fmaxf(a2 + bq[2], 0.f);
                op[3 * TOT] = fmaxf(a3 + bq[3], 0.f);
            }
        }
    }
}

// ---------------------------------------------------------------------------
// fc1 split-K GEMM (unchanged from R2): grid (2,2,145)
// ---------------------------------------------------------------------------
__global__ void fc1_kernel(const float* __restrict__ hist,
                           const float* __restrict__ w1)
{
    __shared__ float As[32 * 68];
    __shared__ float Bs[32 * 68];

    const int m0  = blockIdx.y * 64;
    const int n0  = blockIdx.x * 64;
    const int bz  = blockIdx.z;
    const int tid = threadIdx.x;
    const int ty = tid >> 4, tx = tid & 15;

    float acc[4][4] = {};

    if (bz < NCHUNK - 1) {
        const int kc0 = bz * KCHUNK;
#pragma unroll 1
        for (int kt = 0; kt < KCHUNK; kt += 32) {
            const int kb = kc0 + kt;
#pragma unroll
            for (int l = 0; l < 2; l++) {
                const int idx = tid + l * 256;
                const int row = idx >> 3, kq = idx & 7;
                const float4 v = *reinterpret_cast<const float4*>(
                    g_f3 + (m0 + row) * F3K + kb + kq * 4);
                As[(kq * 4 + 0) * 68 + row] = v.x;
                As[(kq * 4 + 1) * 68 + row] = v.y;
                As[(kq * 4 + 2) * 68 + row] = v.z;
                As[(kq * 4 + 3) * 68 + row] = v.w;
            }
#pragma unroll
            for (int l = 0; l < 4; l++) {
                const int idx = tid + l * 256;
                const int row = idx >> 4, kd = idx & 15;
                const float2 v = *reinterpret_cast<const float2*>(
                    w1 + (n0 + row) * FCK + kb + kd * 2);
                Bs[(kd * 2 + 0) * 68 + row] = v.x;
                Bs[(kd * 2 + 1) * 68 + row] = v.y;
            }
            __syncthreads();
#pragma unroll
            for (int kk = 0; kk < 32; kk++) {
                const float4 a4 = *reinterpret_cast<const float4*>(&As[kk * 68 + ty * 4]);
                const float4 b4 = *reinterpret_cast<const float4*>(&Bs[kk * 68 + tx * 4]);
                const float a[4] = {a4.x, a4.y, a4.z, a4.w};
                const float bb[4] = {b4.x, b4.y, b4.z, b4.w};
#pragma unroll
                for (int i = 0; i < 4; i++)
#pragma unroll
                    for (int j = 0; j < 4; j++)
                        acc[i][j] += a[i] * bb[j];
            }
            __syncthreads();
        }
    } else {
#pragma unroll 1
        for (int kt = 0; kt < 96; kt += 32) {
#pragma unroll
            for (int l = 0; l < 8; l++) {
                const int idx = tid + l * 256;
                const int row = idx >> 5, kk = idx & 31;
                const int k = kt + kk;
                float av = 0.f, bv = 0.f;
                if (k < 90) {
                    av = hist[(m0 + row) * 90 + k];
                    bv = w1[(n0 + row) * FCK + F3K + k];
                }
                As[kk * 68 + row] = av;
                Bs[kk * 68 + row] = bv;
            }
            __syncthreads();
#pragma unroll
            for (int kk = 0; kk < 32; kk++) {
                const float4 a4 = *reinterpret_cast<const float4*>(&As[kk * 68 + ty * 4]);
                const float4 b4 = *reinterpret_cast<const float4*>(&Bs[kk * 68 + tx * 4]);
                const float a[4] = {a4.x, a4.y, a4.z, a4.w};
                const float bb[4] = {b4.x, b4.y, b4.z, b4.w};
#pragma unroll
                for (int i = 0; i < 4; i++)
#pragma unroll
                    for (int j = 0; j < 4; j++)
                        acc[i][j] += a[i] * bb[j];
            }
            __syncthreads();
        }
    }

    float* dst = g_h1p + bz * (BATCH * 128);
#pragma unroll
    for (int i = 0; i < 4; i++)
#pragma unroll
        for (int j = 0; j < 4; j++)
            dst[(m0 + ty * 4 + i) * 128 + (n0 + tx * 4 + j)] = acc[i][j];
}

// ---------------------------------------------------------------------------
// LIF recurrence (unchanged)
// ---------------------------------------------------------------------------
__global__ void lif_kernel(const float* __restrict__ b1,
                           const float* __restrict__ w2,
                           const float* __restrict__ b2,
                           const float* __restrict__ w3,
                           const float* __restrict__ b3,
                           float* __restrict__ out)
{
    extern __shared__ float sm[];
    float* w2s  = sm;
    float* w3s  = w2s + 256 * 129;
    float* spk1 = w3s + 9 * 256;
    float* spk2 = spk1 + 128;

    const int b   = blockIdx.x;
    const int tid = threadIdx.x;

    for (int idx = tid; idx < 256 * 128; idx += blockDim.x) {
        const int j = idx >> 7, i = idx & 127;
        w2s[j * 129 + i] = w2[idx];
    }
    for (int idx = tid; idx < 9 * 256; idx += blockDim.x) w3s[idx] = w3[idx];
    __syncthreads();

    float h1v = 0.f, mem1 = 0.f, syn1 = 0.f;
    if (tid < 128) {
        h1v = b1[tid];
        for (int p = 0; p < NCHUNK; p++)
            h1v += g_h1p[p * (BATCH * 128) + b * 128 + tid];
    }
    float b2v = 0.f, mem2 = 0.f, syn2 = 0.f;
    if (tid < 256) b2v = b2[tid];

    const int w = tid >> 5, lane = tid & 31;
    float b3v = 0.f, mem3 = 0.f, syn3 = 0.f, pot = 0.f;
    if (w < 9 && lane == 0) b3v = b3[w];

    for (int t = 0; t < 10; t++) {
        if (tid < 128) {
            syn1 = 0.9f * syn1 + h1v;
            mem1 = 0.8f * mem1 + syn1;
            const float s = (mem1 > 1.f) ? 1.f : 0.f;
            mem1 -= s;
            spk1[tid] = s;
        }
        __syncthreads();
        if (tid < 256) {
            float h2 = b2v;
#pragma unroll 8
            for (int i = 0; i < 128; i++) h2 += spk1[i] * w2s[tid * 129 + i];
            syn2 = 0.9f * syn2 + h2;
            mem2 = 0.8f * mem2 + syn2;
            const float s = (mem2 > 1.f) ? 1.f : 0.f;
            mem2 -= s;
            spk2[tid] = s;
        }
        __syncthreads();
        if (w < 9) {
            float part = 0.f;
#pragma unroll
            for (int i = 0; i < 8; i++)
                part += spk2[lane + i * 32] * w3s[w * 256 + lane + i * 32];
#pragma unroll
            for (int o = 16; o > 0; o >>= 1)
                part += __shfl_xor_sync(0xffffffff, part, o);
            if (lane == 0) {
                syn3 = 0.9f * syn3 + (part + b3v);
                mem3 = 0.8f * mem3 + syn3;
                pot += mem3;
            }
        }
    }

    if (w < 9 && lane == 0) out[b * 9 + w] = pot * 0.1f;
}

// ---------------------------------------------------------------------------
// Launch
// ---------------------------------------------------------------------------
extern "C" void kernel_launch(void* const* d_in, const int* in_sizes, int n_in,
                              void* d_out, int out_size)
{
    const float* state = (const float*)d_in[0];
    const float* hist  = (const float*)d_in[1];
    const float* cw1   = (const float*)d_in[2];
    const float* cb1   = (const float*)d_in[3];
    const float* cw2   = (const float*)d_in[4];
    const float* cb2   = (const float*)d_in[5];
    const float* cw3   = (const float*)d_in[6];
    const float* cb3   = (const float*)d_in[7];
    const float* w1    = (const float*)d_in[8];
    const float* b1    = (const float*)d_in[9];
    const float* w2    = (const float*)d_in[10];
    const float* b2    = (const float*)d_in[11];
    const float* w3    = (const float*)d_in[12];
    const float* b3    = (const float*)d_in[13];
    float* out = (float*)d_out;

    float* f1;  cudaGetSymbolAddress((void**)&f1, g_f1);
    float* f2;  cudaGetSymbolAddress((void**)&f2, g_f2);
    float* f3;  cudaGetSymbolAddress((void**)&f3, g_f3);
    float* wt1; cudaGetSymbolAddress((void**)&wt1, g_wt1);
    float* wt2; cudaGetSymbolAddress((void**)&wt2, g_wt2);
    float* wt3; cudaGetSymbolAddress((void**)&wt3, g_wt3);

    transpose_w<<<(OC1 * C1 * KK1 * KK1 + 255) / 256, 256>>>(cw1, wt1, OC1, C1 * KK1 * KK1);
    transpose_w<<<(OC2 * C2 * KK2 * KK2 + 255) / 256, 256>>>(cw2, wt2, OC2, C2 * KK2 * KK2);
    transpose_w<<<(OC3 * C3 * KK3 * KK3 + 255) / 256, 256>>>(cw3, wt3, OC3, C3 * KK3 * KK3);

    const int GRID = 444;  // 3 blocks/SM persistent
    // conv1: PT=256, NT=ceil(3025/256)=12
    conv_gemm<C1, H1, W1, KK1, S1, OH1, OW1, OC1, 8, 32, 12>
        <<<GRID, 256>>>(state, wt1, cb1, f1);
    // conv2: PT=128, NT=ceil(676/128)=6
    conv_gemm<C2, H2, W2, KK2, S2, OH2, OW2, OC2, 16, 16, 6>
        <<<GRID, 256>>>(f1, wt2, cb2, f2);
    // conv3: PT=128, NT=ceil(576/128)=5
    conv_gemm<C3, H3, W3, KK3, S3, OH3, OW3, OC3, 16, 16, 5>
        <<<GRID, 256>>>(f2, wt3, cb3, f3);

    fc1_kernel<<<dim3(2, 2, NCHUNK), 256>>>(hist, w1);

    const int lif_smem = (256 * 129 + 9 * 256 + 128 + 256) * (int)sizeof(float);
    cudaFuncSetAttribute(lif_kernel, cudaFuncAttributeMaxDynamicSharedMemorySize,
                         lif_smem);
    lif_kernel<<<BATCH, 320, lif_smem>>>(b1, w2, b2, w3, b3, out);
}

// round 4
// speedup vs baseline: 1.3440x; 1.2215x over previous
#include <cuda_runtime.h>

// ---------------------------------------------------------------------------
// Problem dims
// ---------------------------------------------------------------------------
constexpr int BATCH = 128;
constexpr int C1 = 3,  H1 = 224, W1 = 224, KK1 = 8, S1 = 4, OC1 = 32, OH1 = 55, OW1 = 55;
constexpr int C2 = 32, H2 = 55,  W2 = 55,  KK2 = 4, S2 = 2, OC2 = 64, OH2 = 26, OW2 = 26;
constexpr int C3 = 64, H3 = 26,  W3 = 26,  KK3 = 3, S3 = 1, OC3 = 64, OH3 = 24, OW3 = 24;

constexpr int F3K    = OC3 * OH3 * OW3;   // 36864
constexpr int FCK    = F3K + 90;          // 36954
constexpr int KCHUNK = 256;
constexpr int NCHUNK = F3K / KCHUNK + 1;  // 145

// ---------------------------------------------------------------------------
// Device scratch
// ---------------------------------------------------------------------------
__device__ float  g_f1[BATCH * OC1 * OH1 * OW1];
__device__ float  g_f2[BATCH * OC2 * OH2 * OW2];
__device__ float  g_f3[BATCH * OC3 * OH3 * OW3];
__device__ float  g_h1p[NCHUNK * BATCH * 128];
__device__ float2 g_wt1[KK1 * KK1 * C1 * OC1];   // [k][oc] dup pairs
__device__ float2 g_wt2[KK2 * KK2 * C2 * OC2];
__device__ float2 g_wt3[KK3 * KK3 * C3 * OC3];

typedef unsigned long long u64;

__device__ __forceinline__ void unpack2(u64 v, float& lo, float& hi) {
    asm("mov.b64 {%0, %1}, %2;" : "=f"(lo), "=f"(hi) : "l"(v));
}
__device__ __forceinline__ void ffma2(u64& d, u64 a, u64 b) {
    asm("fma.rn.f32x2 %0, %1, %2, %0;" : "+l"(d) : "l"(a), "l"(b));
}

// ---------------------------------------------------------------------------
// Weight transpose + duplicate: wT2[k][oc] = {w[oc][k], w[oc][k]}
// ---------------------------------------------------------------------------
__global__ void transpose_w2(const float* __restrict__ w, float2* __restrict__ wT,
                             int OC, int CKK)
{
    const int i = blockIdx.x * 256 + threadIdx.x;
    if (i < OC * CKK) {
        const int oc = i / CKK, k = i % CKK;
        const float v = w[i];
        wT[k * OC + oc] = make_float2(v, v);
    }
}

// ---------------------------------------------------------------------------
// Implicit-GEMM conv, position-paired FFMA2:
//   acc[pair][oc] (u64 = 2 positions) += patchpair * {w,w}
// Patches staged un-duplicated (natural pairs), weights staged as dup float2
// (warp-broadcast reads). Per k-step/thread: PP+OCN LDS.64, PP*OCN FFMA2.
// ---------------------------------------------------------------------------
template <int C, int H, int W, int K, int S, int OH, int OW, int OC,
          int OCN, int TY, int PP, int NT>
__global__ void __launch_bounds__((OC / OCN) * TY, 2)
conv_gemm(const float* __restrict__ in, const float2* __restrict__ wT2,
          const float* __restrict__ bias, float* __restrict__ out)
{
    constexpr int KSQ = K * K, CKK = C * KSQ, TOT = OH * OW;
    constexpr int TX = OC / OCN;
    constexpr int THREADS = TX * TY;
    constexpr int PT = TY * PP * 2;
    constexpr int NPP = PT / THREADS;
    static_assert(NPP * THREADS == PT, "PT must be multiple of THREADS");
    static_assert(CKK % 16 == 0, "CKK multiple of 16");

    __shared__ float  Ps[16 * PT];
    __shared__ float2 Ws[16 * OC];

    const int tid = threadIdx.x;
    const int tx = tid / TY, ty = tid % TY;

    const int bt = blockIdx.x;
    const int b = bt / NT, tile = bt % NT;
    const int p0 = tile * PT;

    // per-tile staging base pointers (position -> input origin), clamped
    const float* bp[NPP];
#pragma unroll
    for (int j = 0; j < NPP; j++) {
        int pp = p0 + tid + j * THREADS;
        if (pp >= TOT) pp = TOT - 1;
        const int oh = pp / OW, ow = pp % OW;
        bp[j] = in + ((b * C) * H + oh * S) * W + ow * S;
    }

    float bq[OCN];
#pragma unroll
    for (int j = 0; j < OCN; j++) bq[j] = bias[tx * OCN + j];

    u64 acc[PP][OCN];
#pragma unroll
    for (int i = 0; i < PP; i++)
#pragma unroll
        for (int j = 0; j < OCN; j++) acc[i][j] = 0ull;

    for (int kc = 0; kc < CKK; kc += 16) {
        __syncthreads();
        // stage weights (contiguous copy of rows kc..kc+15)
#pragma unroll
        for (int e = tid; e < 16 * OC; e += THREADS)
            Ws[e] = wT2[kc * OC + e];
        // stage patches: thread owns fixed position(s), only k-offset varies
#pragma unroll
        for (int l = 0; l < 16 * NPP; l++) {
            const int kk = l / NPP, j = l % NPP;
            const int k = kc + kk;
            const int c = k / KSQ, r = k % KSQ;
            const int kh = r / K, kw = r % K;
            Ps[kk * PT + tid + j * THREADS] = __ldg(bp[j] + (c * H + kh) * W + kw);
        }
        __syncthreads();
        // compute
#pragma unroll
        for (int kk = 0; kk < 16; kk++) {
            u64 wv[OCN], av[PP];
#pragma unroll
            for (int j = 0; j < OCN; j++)
                wv[j] = *reinterpret_cast<const u64*>(&Ws[kk * OC + tx * OCN + j]);
#pragma unroll
            for (int i = 0; i < PP; i++)
                av[i] = *reinterpret_cast<const u64*>(&Ps[kk * PT + 2 * (ty + i * TY)]);
#pragma unroll
            for (int i = 0; i < PP; i++)
#pragma unroll
                for (int j = 0; j < OCN; j++)
                    ffma2(acc[i][j], av[i], wv[j]);
        }
    }

    // epilogue: bias + ReLU
#pragma unroll
    for (int i = 0; i < PP; i++) {
        const int pos = p0 + 2 * (ty + i * TY);
#pragma unroll
        for (int j = 0; j < OCN; j++) {
            float a0, a1;
            unpack2(acc[i][j], a0, a1);
            float* op = out + (b * OC + tx * OCN + j) * TOT;
            if (pos < TOT)     op[pos]     = fmaxf(a0 + bq[j], 0.f);
            if (pos + 1 < TOT) op[pos + 1] = fmaxf(a1 + bq[j], 0.f);
        }
    }
}

// ---------------------------------------------------------------------------
// fc1 split-K GEMM (R2 structure): grid (2,2,145)
// ---------------------------------------------------------------------------
__global__ void fc1_kernel(const float* __restrict__ hist,
                           const float* __restrict__ w1)
{
    __shared__ float As[32 * 68];
    __shared__ float Bs[32 * 68];

    const int m0  = blockIdx.y * 64;
    const int n0  = blockIdx.x * 64;
    const int bz  = blockIdx.z;
    const int tid = threadIdx.x;
    const int ty = tid >> 4, tx = tid & 15;

    float acc[4][4] = {};

    if (bz < NCHUNK - 1) {
        const int kc0 = bz * KCHUNK;
#pragma unroll 1
        for (int kt = 0; kt < KCHUNK; kt += 32) {
            const int kb = kc0 + kt;
#pragma unroll
            for (int l = 0; l < 2; l++) {
                const int idx = tid + l * 256;
                const int row = idx >> 3, kq = idx & 7;
                const float4 v = *reinterpret_cast<const float4*>(
                    g_f3 + (m0 + row) * F3K + kb + kq * 4);
                As[(kq * 4 + 0) * 68 + row] = v.x;
                As[(kq * 4 + 1) * 68 + row] = v.y;
                As[(kq * 4 + 2) * 68 + row] = v.z;
                As[(kq * 4 + 3) * 68 + row] = v.w;
            }
#pragma unroll
            for (int l = 0; l < 4; l++) {
                const int idx = tid + l * 256;
                const int row = idx >> 4, kd = idx & 15;
                const float2 v = *reinterpret_cast<const float2*>(
                    w1 + (n0 + row) * FCK + kb + kd * 2);
                Bs[(kd * 2 + 0) * 68 + row] = v.x;
                Bs[(kd * 2 + 1) * 68 + row] = v.y;
            }
            __syncthreads();
#pragma unroll
            for (int kk = 0; kk < 32; kk++) {
                const float4 a4 = *reinterpret_cast<const float4*>(&As[kk * 68 + ty * 4]);
                const float4 b4 = *reinterpret_cast<const float4*>(&Bs[kk * 68 + tx * 4]);
                const float a[4] = {a4.x, a4.y, a4.z, a4.w};
                const float bb[4] = {b4.x, b4.y, b4.z, b4.w};
#pragma unroll
                for (int i = 0; i < 4; i++)
#pragma unroll
                    for (int j = 0; j < 4; j++)
                        acc[i][j] += a[i] * bb[j];
            }
            __syncthreads();
        }
    } else {
#pragma unroll 1
        for (int kt = 0; kt < 96; kt += 32) {
#pragma unroll
            for (int l = 0; l < 8; l++) {
                const int idx = tid + l * 256;
                const int row = idx >> 5, kk = idx & 31;
                const int k = kt + kk;
                float av = 0.f, bv = 0.f;
                if (k < 90) {
                    av = hist[(m0 + row) * 90 + k];
                    bv = w1[(n0 + row) * FCK + F3K + k];
                }
                As[kk * 68 + row] = av;
                Bs[kk * 68 + row] = bv;
            }
            __syncthreads();
#pragma unroll
            for (int kk = 0; kk < 32; kk++) {
                const float4 a4 = *reinterpret_cast<const float4*>(&As[kk * 68 + ty * 4]);
                const float4 b4 = *reinterpret_cast<const float4*>(&Bs[kk * 68 + tx * 4]);
                const float a[4] = {a4.x, a4.y, a4.z, a4.w};
                const float bb[4] = {b4.x, b4.y, b4.z, b4.w};
#pragma unroll
                for (int i = 0; i < 4; i++)
#pragma unroll
                    for (int j = 0; j < 4; j++)
                        acc[i][j] += a[i] * bb[j];
            }
            __syncthreads();
        }
    }

    float* dst = g_h1p + bz * (BATCH * 128);
#pragma unroll
    for (int i = 0; i < 4; i++)
#pragma unroll
        for (int j = 0; j < 4; j++)
            dst[(m0 + ty * 4 + i) * 128 + (n0 + tx * 4 + j)] = acc[i][j];
}

// ---------------------------------------------------------------------------
// LIF recurrence (unchanged)
// ---------------------------------------------------------------------------
__global__ void lif_kernel(const float* __restrict__ b1,
                           const float* __restrict__ w2,
                           const float* __restrict__ b2,
                           const float* __restrict__ w3,
                           const float* __restrict__ b3,
                           float* __restrict__ out)
{
    extern __shared__ float sm[];
    float* w2s  = sm;
    float* w3s  = w2s + 256 * 129;
    float* spk1 = w3s + 9 * 256;
    float* spk2 = spk1 + 128;

    const int b   = blockIdx.x;
    const int tid = threadIdx.x;

    for (int idx = tid; idx < 256 * 128; idx += blockDim.x) {
        const int j = idx >> 7, i = idx & 127;
        w2s[j * 129 + i] = w2[idx];
    }
    for (int idx = tid; idx < 9 * 256; idx += blockDim.x) w3s[idx] = w3[idx];
    __syncthreads();

    float h1v = 0.f, mem1 = 0.f, syn1 = 0.f;
    if (tid < 128) {
        h1v = b1[tid];
        for (int p = 0; p < NCHUNK; p++)
            h1v += g_h1p[p * (BATCH * 128) + b * 128 + tid];
    }
    float b2v = 0.f, mem2 = 0.f, syn2 = 0.f;
    if (tid < 256) b2v = b2[tid];

    const int w = tid >> 5, lane = tid & 31;
    float b3v = 0.f, mem3 = 0.f, syn3 = 0.f, pot = 0.f;
    if (w < 9 && lane == 0) b3v = b3[w];

    for (int t = 0; t < 10; t++) {
        if (tid < 128) {
            syn1 = 0.9f * syn1 + h1v;
            mem1 = 0.8f * mem1 + syn1;
            const float s = (mem1 > 1.f) ? 1.f : 0.f;
            mem1 -= s;
            spk1[tid] = s;
        }
        __syncthreads();
        if (tid < 256) {
            float h2 = b2v;
#pragma unroll 8
            for (int i = 0; i < 128; i++) h2 += spk1[i] * w2s[tid * 129 + i];
            syn2 = 0.9f * syn2 + h2;
            mem2 = 0.8f * mem2 + syn2;
            const float s = (mem2 > 1.f) ? 1.f : 0.f;
            mem2 -= s;
            spk2[tid] = s;
        }
        __syncthreads();
        if (w < 9) {
            float part = 0.f;
#pragma unroll
            for (int i = 0; i < 8; i++)
                part += spk2[lane + i * 32] * w3s[w * 256 + lane + i * 32];
#pragma unroll
            for (int o = 16; o > 0; o >>= 1)
                part += __shfl_xor_sync(0xffffffff, part, o);
            if (lane == 0) {
                syn3 = 0.9f * syn3 + (part + b3v);
                mem3 = 0.8f * mem3 + syn3;
                pot += mem3;
            }
        }
    }

    if (w < 9 && lane == 0) out[b * 9 + w] = pot * 0.1f;
}

// ---------------------------------------------------------------------------
// Launch
// ---------------------------------------------------------------------------
extern "C" void kernel_launch(void* const* d_in, const int* in_sizes, int n_in,
                              void* d_out, int out_size)
{
    const float* state = (const float*)d_in[0];
    const float* hist  = (const float*)d_in[1];
    const float* cw1   = (const float*)d_in[2];
    const float* cb1   = (const float*)d_in[3];
    const float* cw2   = (const float*)d_in[4];
    const float* cb2   = (const float*)d_in[5];
    const float* cw3   = (const float*)d_in[6];
    const float* cb3   = (const float*)d_in[7];
    const float* w1    = (const float*)d_in[8];
    const float* b1    = (const float*)d_in[9];
    const float* w2    = (const float*)d_in[10];
    const float* b2    = (const float*)d_in[11];
    const float* w3    = (const float*)d_in[12];
    const float* b3    = (const float*)d_in[13];
    float* out = (float*)d_out;

    float*  f1;  cudaGetSymbolAddress((void**)&f1,  g_f1);
    float*  f2;  cudaGetSymbolAddress((void**)&f2,  g_f2);
    float*  f3;  cudaGetSymbolAddress((void**)&f3,  g_f3);
    float2* wt1; cudaGetSymbolAddress((void**)&wt1, g_wt1);
    float2* wt2; cudaGetSymbolAddress((void**)&wt2, g_wt2);
    float2* wt3; cudaGetSymbolAddress((void**)&wt3, g_wt3);

    transpose_w2<<<(OC1 * C1 * KK1 * KK1 + 255) / 256, 256>>>(cw1, wt1, OC1, C1 * KK1 * KK1);
    transpose_w2<<<(OC2 * C2 * KK2 * KK2 + 255) / 256, 256>>>(cw2, wt2, OC2, C2 * KK2 * KK2);
    transpose_w2<<<(OC3 * C3 * KK3 * KK3 + 255) / 256, 256>>>(cw3, wt3, OC3, C3 * KK3 * KK3);

    // conv1: OCN=8,TY=64,PP=4 -> PT=512, NT=6, 256 thr, grid 768
    conv_gemm<C1, H1, W1, KK1, S1, OH1, OW1, OC1, 8, 64, 4, 6>
        <<<BATCH * 6, 256>>>(state, wt1, cb1, f1);
    // conv2: OCN=8,TY=32,PP=4 -> PT=256, NT=3, 256 thr, grid 384
    conv_gemm<C2, H2, W2, KK2, S2, OH2, OW2, OC2, 8, 32, 4, 3>
        <<<BATCH * 3, 256>>>(f1, wt2, cb2, f2);
    // conv3: OCN=8,TY=36,PP=4 -> PT=288, NT=2 (exact 576), 288 thr, grid 256
    conv_gemm<C3, H3, W3, KK3, S3, OH3, OW3, OC3, 8, 36, 4, 2>
        <<<BATCH * 2, 288>>>(f2, wt3, cb3, f3);

    fc1_kernel<<<dim3(2, 2, NCHUNK), 256>>>(hist, w1);

    const int lif_smem = (256 * 129 + 9 * 256 + 128 + 256) * (int)sizeof(float);
    cudaFuncSetAttribute(lif_kernel, cudaFuncAttributeMaxDynamicSharedMemorySize,
                         lif_smem);
    lif_kernel<<<BATCH, 320, lif_smem>>>(b1, w2, b2, w3, b3, out);
}

// round 5
// speedup vs baseline: 1.3586x; 1.0108x over previous
#include <cuda_runtime.h>

// ---------------------------------------------------------------------------
// Problem dims
// ---------------------------------------------------------------------------
constexpr int BATCH = 128;
constexpr int C1 = 3,  H1 = 224, W1 = 224, KK1 = 8, S1 = 4, OC1 = 32, OH1 = 55, OW1 = 55;
constexpr int C2 = 32, H2 = 55,  W2 = 55,  KK2 = 4, S2 = 2, OC2 = 64, OH2 = 26, OW2 = 26;
constexpr int C3 = 64, H3 = 26,  W3 = 26,  KK3 = 3, S3 = 1, OC3 = 64, OH3 = 24, OW3 = 24;

constexpr int TOT1 = OH1 * OW1;          // 3025
constexpr int TOT2 = OH2 * OW2;          // 676
constexpr int TOT3 = OH3 * OW3;          // 576
constexpr int ST1  = 3028;               // padded plane stride for f1 (16B rows)

constexpr int F3K    = TOT3 * OC3;       // 36864
constexpr int FCK    = F3K + 90;         // 36954
constexpr int KCHUNK = 256;
constexpr int NCHUNK = F3K / KCHUNK + 1; // 145

// ---------------------------------------------------------------------------
// Device scratch
// ---------------------------------------------------------------------------
__device__ float  g_f1[BATCH * OC1 * ST1];
__device__ float  g_f2[BATCH * OC2 * TOT2];
__device__ float  g_f3[BATCH * OC3 * TOT3];
__device__ float  g_h1p[NCHUNK * BATCH * 128];
__device__ __align__(16) float2 g_wt1[KK1 * KK1 * C1 * OC1];
__device__ __align__(16) float2 g_wt2[KK2 * KK2 * C2 * OC2];
__device__ __align__(16) float2 g_wt3[KK3 * KK3 * C3 * OC3];

typedef unsigned long long u64;

__device__ __forceinline__ void unpack2(u64 v, float& lo, float& hi) {
    asm("mov.b64 {%0, %1}, %2;" : "=f"(lo), "=f"(hi) : "l"(v));
}
__device__ __forceinline__ void ffma2(u64& d, u64 a, u64 b) {
    asm("fma.rn.f32x2 %0, %1, %2, %0;" : "+l"(d) : "l"(a), "l"(b));
}
__device__ __forceinline__ unsigned su32(const void* p) {
    return (unsigned)__cvta_generic_to_shared(p);
}
__device__ __forceinline__ void cp4(unsigned dst, const float* src) {
    asm volatile("cp.async.ca.shared.global [%0], [%1], 4;\n" :: "r"(dst), "l"(src));
}
__device__ __forceinline__ void cp16(unsigned dst, const void* src) {
    asm volatile("cp.async.cg.shared.global [%0], [%1], 16;\n" :: "r"(dst), "l"(src));
}
__device__ __forceinline__ void cp_commit() {
    asm volatile("cp.async.commit_group;\n");
}
template <int N> __device__ __forceinline__ void cp_wait() {
    asm volatile("cp.async.wait_group %0;\n" :: "n"(N));
}

// ---------------------------------------------------------------------------
// Weight transpose + duplicate: wT2[k][oc] = {w[oc][k], w[oc][k]}
// ---------------------------------------------------------------------------
__global__ void transpose_w2(const float* __restrict__ w, float2* __restrict__ wT,
                             int OC, int CKK)
{
    const int i = blockIdx.x * 256 + threadIdx.x;
    if (i < OC * CKK) {
        const int oc = i / CKK, k = i % CKK;
        const float v = w[i];
        wT[k * OC + oc] = make_float2(v, v);
    }
}

// ---------------------------------------------------------------------------
// Implicit-GEMM conv, position-paired FFMA2, cp.async double-buffered.
//   PS  = input plane stride (floats per (b,c) plane)
//   OST = output plane stride
// Per k-step/thread: 2+OCN/2 LDS.128 feeding PP*OCN FFMA2.
// ---------------------------------------------------------------------------
template <int C, int W, int PS, int K, int S, int TOT, int OW, int OC,
          int OCN, int TY, int PP, int NT, int OST>
__global__ void __launch_bounds__((OC / OCN) * TY, 2)
conv_gemm(const float* __restrict__ in, const float2* __restrict__ wT2,
          const float* __restrict__ bias, float* __restrict__ out)
{
    constexpr int KSQ = K * K, CKK = C * KSQ;
    constexpr int TX = OC / OCN;
    constexpr int THREADS = TX * TY;
    constexpr int PT = TY * PP * 2;
    constexpr int NPP = PT / THREADS;
    constexpr int NCH = CKK / 16;
    static_assert(NPP * THREADS == PT, "PT multiple of THREADS");
    static_assert(CKK % 16 == 0, "CKK multiple of 16");
    static_assert((OCN & 1) == 0 && (PP & 1) == 0, "even tiles");

    extern __shared__ char smraw[];
    float*  Ps = (float*)smraw;                                 // 2 * 16*PT
    float2* Ws = (float2*)(smraw + 2 * 16 * PT * sizeof(float)); // 2 * 16*OC

    const int tid = threadIdx.x;
    const int tx = tid / TY, ty = tid % TY;

    const int bt = blockIdx.x;
    const int b = bt / NT, tile = bt % NT;
    const int p0 = tile * PT;

    // staging base pointers (fixed positions per thread), clamped
    const float* bp[NPP];
#pragma unroll
    for (int j = 0; j < NPP; j++) {
        int pp = p0 + tid + j * THREADS;
        if (pp >= TOT) pp = TOT - 1;
        const int oh = pp / OW, ow = pp % OW;
        bp[j] = in + (b * C) * PS + (oh * S) * W + ow * S;
    }

    float bq[OCN];
#pragma unroll
    for (int j = 0; j < OCN; j++) bq[j] = bias[tx * OCN + j];

    u64 acc[PP][OCN];
#pragma unroll
    for (int i = 0; i < PP; i++)
#pragma unroll
        for (int j = 0; j < OCN; j++) acc[i][j] = 0ull;

    auto stage = [&](int buf, int kc) {
        float2* Wb = Ws + buf * 16 * OC;
        for (int e = tid; e < 16 * OC / 2; e += THREADS)
            cp16(su32(Wb + e * 2), wT2 + kc * OC + e * 2);
        float* Pb = Ps + buf * 16 * PT;
#pragma unroll
        for (int kk = 0; kk < 16; kk++) {
            const int k = kc + kk;
            const int c = k / KSQ, r = k - c * KSQ;
            const int kh = r / K, kw = r - kh * K;
            const int off = c * PS + kh * W + kw;
#pragma unroll
            for (int j = 0; j < NPP; j++)
                cp4(su32(Pb + kk * PT + tid + j * THREADS), bp[j] + off);
        }
        cp_commit();
    };

    int buf = 0;
    stage(0, 0);
    for (int ch = 0; ch < NCH; ch++) {
        if (ch + 1 < NCH) { stage(buf ^ 1, (ch + 1) * 16); cp_wait<1>(); }
        else              { cp_wait<0>(); }
        __syncthreads();

        const float*  Pb = Ps + buf * 16 * PT;
        const float2* Wb = Ws + buf * 16 * OC;
#pragma unroll
        for (int kk = 0; kk < 16; kk++) {
            u64 wv[OCN], av[PP];
            const ulonglong2* wp =
                reinterpret_cast<const ulonglong2*>(Wb + kk * OC + tx * OCN);
#pragma unroll
            for (int j = 0; j < OCN / 2; j++) {
                const ulonglong2 t = wp[j];
                wv[2 * j] = t.x; wv[2 * j + 1] = t.y;
            }
            const ulonglong2* pa =
                reinterpret_cast<const ulonglong2*>(Pb + kk * PT + ty * PP * 2);
#pragma unroll
            for (int i = 0; i < PP / 2; i++) {
                const ulonglong2 t = pa[i];
                av[2 * i] = t.x; av[2 * i + 1] = t.y;
            }
#pragma unroll
            for (int i = 0; i < PP; i++)
#pragma unroll
                for (int j = 0; j < OCN; j++)
                    ffma2(acc[i][j], av[i], wv[j]);
        }
        __syncthreads();
        buf ^= 1;
    }

    // epilogue: bias + ReLU, vectorized stores
    const int pos0 = p0 + ty * PP * 2;
    const bool full = (pos0 + PP * 2 <= TOT);
#pragma unroll
    for (int j = 0; j < OCN; j++) {
        float v[PP * 2];
#pragma unroll
        for (int i = 0; i < PP; i++) {
            float a0, a1;
            unpack2(acc[i][j], a0, a1);
            v[2 * i]     = fmaxf(a0 + bq[j], 0.f);
            v[2 * i + 1] = fmaxf(a1 + bq[j], 0.f);
        }
        float* op = out + (b * OC + tx * OCN + j) * OST + pos0;
        if (full) {
#pragma unroll
            for (int q = 0; q < PP / 2; q++)
                reinterpret_cast<float4*>(op)[q] =
                    make_float4(v[4 * q], v[4 * q + 1], v[4 * q + 2], v[4 * q + 3]);
        } else {
#pragma unroll
            for (int e = 0; e < PP * 2; e++)
                if (pos0 + e < TOT) op[e] = v[e];
        }
    }
}

// ---------------------------------------------------------------------------
// fc1 split-K GEMM: grid (2,2,145)
// ---------------------------------------------------------------------------
__global__ void fc1_kernel(const float* __restrict__ hist,
                           const float* __restrict__ w1)
{
    __shared__ float As[32 * 68];
    __shared__ float Bs[32 * 68];

    const int m0  = blockIdx.y * 64;
    const int n0  = blockIdx.x * 64;
    const int bz  = blockIdx.z;
    const int tid = threadIdx.x;
    const int ty = tid >> 4, tx = tid & 15;

    float acc[4][4] = {};

    if (bz < NCHUNK - 1) {
        const int kc0 = bz * KCHUNK;
#pragma unroll 1
        for (int kt = 0; kt < KCHUNK; kt += 32) {
            const int kb = kc0 + kt;
#pragma unroll
            for (int l = 0; l < 2; l++) {
                const int idx = tid + l * 256;
                const int row = idx >> 3, kq = idx & 7;
                const float4 v = *reinterpret_cast<const float4*>(
                    g_f3 + (m0 + row) * F3K + kb + kq * 4);
                As[(kq * 4 + 0) * 68 + row] = v.x;
                As[(kq * 4 + 1) * 68 + row] = v.y;
                As[(kq * 4 + 2) * 68 + row] = v.z;
                As[(kq * 4 + 3) * 68 + row] = v.w;
            }
#pragma unroll
            for (int l = 0; l < 4; l++) {
                const int idx = tid + l * 256;
                const int row = idx >> 4, kd = idx & 15;
                const float2 v = *reinterpret_cast<const float2*>(
                    w1 + (n0 + row) * FCK + kb + kd * 2);
                Bs[(kd * 2 + 0) * 68 + row] = v.x;
                Bs[(kd * 2 + 1) * 68 + row] = v.y;
            }
            __syncthreads();
#pragma unroll
            for (int kk = 0; kk < 32; kk++) {
                const float4 a4 = *reinterpret_cast<const float4*>(&As[kk * 68 + ty * 4]);
                const float4 b4 = *reinterpret_cast<const float4*>(&Bs[kk * 68 + tx * 4]);
                const float a[4] = {a4.x, a4.y, a4.z, a4.w};
                const float bb[4] = {b4.x, b4.y, b4.z, b4.w};
#pragma unroll
                for (int i = 0; i < 4; i++)
#pragma unroll
                    for (int j = 0; j < 4; j++)
                        acc[i][j] += a[i] * bb[j];
            }
            __syncthreads();
        }
    } else {
#pragma unroll 1
        for (int kt = 0; kt < 96; kt += 32) {
#pragma unroll
            for (int l = 0; l < 8; l++) {
                const int idx = tid + l * 256;
                const int row = idx >> 5, kk = idx & 31;
                const int k = kt + kk;
                float av = 0.f, bv = 0.f;
                if (k < 90) {
                    av = hist[(m0 + row) * 90 + k];
                    bv = w1[(n0 + row) * FCK + F3K + k];
                }
                As[kk * 68 + row] = av;
                Bs[kk * 68 + row] = bv;
            }
            __syncthreads();
#pragma unroll
            for (int kk = 0; kk < 32; kk++) {
                const float4 a4 = *reinterpret_cast<const float4*>(&As[kk * 68 + ty * 4]);
                const float4 b4 = *reinterpret_cast<const float4*>(&Bs[kk * 68 + tx * 4]);
                const float a[4] = {a4.x, a4.y, a4.z, a4.w};
                const float bb[4] = {b4.x, b4.y, b4.z, b4.w};
#pragma unroll
                for (int i = 0; i < 4; i++)
#pragma unroll
                    for (int j = 0; j < 4; j++)
                        acc[i][j] += a[i] * bb[j];
            }
            __syncthreads();
        }
    }

    float* dst = g_h1p + bz * (BATCH * 128);
#pragma unroll
    for (int i = 0; i < 4; i++)
#pragma unroll
        for (int j = 0; j < 4; j++)
            dst[(m0 + ty * 4 + i) * 128 + (n0 + tx * 4 + j)] = acc[i][j];
}

// ---------------------------------------------------------------------------
// LIF recurrence (unchanged)
// ---------------------------------------------------------------------------
__global__ void lif_kernel(const float* __restrict__ b1,
                           const float* __restrict__ w2,
                           const float* __restrict__ b2,
                           const float* __restrict__ w3,
                           const float* __restrict__ b3,
                           float* __restrict__ out)
{
    extern __shared__ float sm[];
    float* w2s  = sm;
    float* w3s  = w2s + 256 * 129;
    float* spk1 = w3s + 9 * 256;
    float* spk2 = spk1 + 128;

    const int b   = blockIdx.x;
    const int tid = threadIdx.x;

    for (int idx = tid; idx < 256 * 128; idx += blockDim.x) {
        const int j = idx >> 7, i = idx & 127;
        w2s[j * 129 + i] = w2[idx];
    }
    for (int idx = tid; idx < 9 * 256; idx += blockDim.x) w3s[idx] = w3[idx];
    __syncthreads();

    float h1v = 0.f, mem1 = 0.f, syn1 = 0.f;
    if (tid < 128) {
        h1v = b1[tid];
        for (int p = 0; p < NCHUNK; p++)
            h1v += g_h1p[p * (BATCH * 128) + b * 128 + tid];
    }
    float b2v = 0.f, mem2 = 0.f, syn2 = 0.f;
    if (tid < 256) b2v = b2[tid];

    const int w = tid >> 5, lane = tid & 31;
    float b3v = 0.f, mem3 = 0.f, syn3 = 0.f, pot = 0.f;
    if (w < 9 && lane == 0) b3v = b3[w];

    for (int t = 0; t < 10; t++) {
        if (tid < 128) {
            syn1 = 0.9f * syn1 + h1v;
            mem1 = 0.8f * mem1 + syn1;
            const float s = (mem1 > 1.f) ? 1.f : 0.f;
            mem1 -= s;
            spk1[tid] = s;
        }
        __syncthreads();
        if (tid < 256) {
            float h2 = b2v;
#pragma unroll 8
            for (int i = 0; i < 128; i++) h2 += spk1[i] * w2s[tid * 129 + i];
            syn2 = 0.9f * syn2 + h2;
            mem2 = 0.8f * mem2 + syn2;
            const float s = (mem2 > 1.f) ? 1.f : 0.f;
            mem2 -= s;
            spk2[tid] = s;
        }
        __syncthreads();
        if (w < 9) {
            float part = 0.f;
#pragma unroll
            for (int i = 0; i < 8; i++)
                part += spk2[lane + i * 32] * w3s[w * 256 + lane + i * 32];
#pragma unroll
            for (int o = 16; o > 0; o >>= 1)
                part += __shfl_xor_sync(0xffffffff, part, o);
            if (lane == 0) {
                syn3 = 0.9f * syn3 + (part + b3v);
                mem3 = 0.8f * mem3 + syn3;
                pot += mem3;
            }
        }
    }

    if (w < 9 && lane == 0) out[b * 9 + w] = pot * 0.1f;
}

// ---------------------------------------------------------------------------
// Launch
// ---------------------------------------------------------------------------
extern "C" void kernel_launch(void* const* d_in, const int* in_sizes, int n_in,
                              void* d_out, int out_size)
{
    const float* state = (const float*)d_in[0];
    const float* hist  = (const float*)d_in[1];
    const float* cw1   = (const float*)d_in[2];
    const float* cb1   = (const float*)d_in[3];
    const float* cw2   = (const float*)d_in[4];
    const float* cb2   = (const float*)d_in[5];
    const float* cw3   = (const float*)d_in[6];
    const float* cb3   = (const float*)d_in[7];
    const float* w1    = (const float*)d_in[8];
    const float* b1    = (const float*)d_in[9];
    const float* w2    = (const float*)d_in[10];
    const float* b2    = (const float*)d_in[11];
    const float* w3    = (const float*)d_in[12];
    const float* b3    = (const float*)d_in[13];
    float* out = (float*)d_out;

    float*  f1;  cudaGetSymbolAddress((void**)&f1,  g_f1);
    float*  f2;  cudaGetSymbolAddress((void**)&f2,  g_f2);
    float*  f3;  cudaGetSymbolAddress((void**)&f3,  g_f3);
    float2* wt1; cudaGetSymbolAddress((void**)&wt1, g_wt1);
    float2* wt2; cudaGetSymbolAddress((void**)&wt2, g_wt2);
    float2* wt3; cudaGetSymbolAddress((void**)&wt3, g_wt3);

    transpose_w2<<<(OC1 * C1 * KK1 * KK1 + 255) / 256, 256>>>(cw1, wt1, OC1, C1 * KK1 * KK1);
    transpose_w2<<<(OC2 * C2 * KK2 * KK2 + 255) / 256, 256>>>(cw2, wt2, OC2, C2 * KK2 * KK2);
    transpose_w2<<<(OC3 * C3 * KK3 * KK3 + 255) / 256, 256>>>(cw3, wt3, OC3, C3 * KK3 * KK3);

    // conv1: OCN=8,TY=64,PP=4 -> PT=512, NT=6, 256 thr
    {
        auto kfn = conv_gemm<C1, W1, H1 * W1, KK1, S1, TOT1, OW1, OC1, 8, 64, 4, 6, ST1>;
        const int smem = 2 * 16 * 512 * 4 + 2 * 16 * OC1 * 8;   // 73728
        cudaFuncSetAttribute(kfn, cudaFuncAttributeMaxDynamicSharedMemorySize, smem);
        kfn<<<BATCH * 6, 256, smem>>>(state, wt1, cb1, f1);
    }
    // conv2: OCN=8,TY=32,PP=4 -> PT=256, NT=3, 256 thr (input f1 plane stride ST1)
    {
        auto kfn = conv_gemm<C2, W2, ST1, KK2, S2, TOT2, OW2, OC2, 8, 32, 4, 3, TOT2>;
        const int smem = 2 * 16 * 256 * 4 + 2 * 16 * OC2 * 8;   // 49152
        cudaFuncSetAttribute(kfn, cudaFuncAttributeMaxDynamicSharedMemorySize, smem);
        kfn<<<BATCH * 3, 256, smem>>>(f1, wt2, cb2, f2);
    }
    // conv3: OCN=8,TY=36,PP=4 -> PT=288, NT=2 (exact), 288 thr
    {
        auto kfn = conv_gemm<C3, W3, TOT2, KK3, S3, TOT3, OW3, OC3, 8, 36, 4, 2, TOT3>;
        const int smem = 2 * 16 * 288 * 4 + 2 * 16 * OC3 * 8;   // 53248
        cudaFuncSetAttribute(kfn, cudaFuncAttributeMaxDynamicSharedMemorySize, smem);
        kfn<<<BATCH * 2, 288, smem>>>(f2, wt3, cb3, f3);
    }

    fc1_kernel<<<dim3(2, 2, NCHUNK), 256>>>(hist, w1);

    const int lif_smem = (256 * 129 + 9 * 256 + 128 + 256) * (int)sizeof(float);
    cudaFuncSetAttribute(lif_kernel, cudaFuncAttributeMaxDynamicSharedMemorySize,
                         lif_smem);
    lif_kernel<<<BATCH, 320, lif_smem>>>(b1, w2, b2, w3, b3, out);
}

// round 8
// speedup vs baseline: 1.3784x; 1.0146x over previous
#include <cuda_runtime.h>

// ---------------------------------------------------------------------------
// Problem dims
// ---------------------------------------------------------------------------
constexpr int BATCH = 128;
constexpr int C1 = 3,  H1 = 224, W1 = 224, KK1 = 8, S1 = 4, OC1 = 32, OH1 = 55, OW1 = 55;
constexpr int OC2 = 64, OH2 = 26, OW2 = 26;   // conv2 out
constexpr int OC3 = 64, OH3 = 24, OW3 = 24;   // conv3 out

constexpr int TOT1 = OH1 * OW1;          // 3025
constexpr int TOT3 = OH3 * OW3;          // 576

// conv1 output in phase-split layout: 128 planes (32 oc x 2x2 phase) of 28x28
constexpr int C2P  = 128;                // conv2' input channels
constexpr int P1S  = 28 * 28;            // 784 plane stride
// conv2' output: padded rows (28) for aligned conv3 staging
constexpr int F2WS = 28;
constexpr int F2PS = OH2 * F2WS;         // 728

constexpr int F3K    = TOT3 * OC3;       // 36864
constexpr int FCK    = F3K + 90;         // 36954
constexpr int KCHUNK = 256;
constexpr int NCHUNK = F3K / KCHUNK + 1; // 145

// ---------------------------------------------------------------------------
// Device scratch
// ---------------------------------------------------------------------------
__device__ float  g_f1ps[BATCH * C2P * P1S];           // 51.4 MB
__device__ float  g_f2[BATCH * OC2 * F2PS];            // 23.9 MB
__device__ float  g_f3[BATCH * OC3 * TOT3];            // 18.9 MB
__device__ float  g_h1p[NCHUNK * BATCH * 128];
__device__ __align__(16) float2 g_wt1[192 * OC1];      // conv1 dup-pair wT
__device__ __align__(16) float2 g_wt2[C2P * 4 * OC2];  // conv2' (128ch,2x2) dup
__device__ __align__(16) float2 g_wt3[64 * 9 * OC3];   // conv3  (64ch,3x3) dup

typedef unsigned long long u64;

__device__ __forceinline__ u64 pack2(float lo, float hi) {
    u64 r; asm("mov.b64 %0, {%1, %2};" : "=l"(r) : "f"(lo), "f"(hi)); return r;
}
__device__ __forceinline__ void unpack2(u64 v, float& lo, float& hi) {
    asm("mov.b64 {%0, %1}, %2;" : "=f"(lo), "=f"(hi) : "l"(v));
}
__device__ __forceinline__ void ffma2(u64& d, u64 a, u64 b) {
    asm("fma.rn.f32x2 %0, %1, %2, %0;" : "+l"(d) : "l"(a), "l"(b));
}
__device__ __forceinline__ unsigned su32(const void* p) {
    return (unsigned)__cvta_generic_to_shared(p);
}
__device__ __forceinline__ void cp16(unsigned dst, const void* src) {
    asm volatile("cp.async.cg.shared.global [%0], [%1], 16;\n" :: "r"(dst), "l"(src));
}
__device__ __forceinline__ void cp_commit() { asm volatile("cp.async.commit_group;\n"); }
template <int N> __device__ __forceinline__ void cp_wait() {
    asm volatile("cp.async.wait_group %0;\n" :: "n"(N));
}

// ---------------------------------------------------------------------------
// Weight prep
// ---------------------------------------------------------------------------
__global__ void transpose_w2(const float* __restrict__ w, float2* __restrict__ wT,
                             int OC, int CKK)
{
    const int i = blockIdx.x * 256 + threadIdx.x;
    if (i < OC * CKK) {
        const int oc = i / CKK, k = i % CKK;
        const float v = w[i];
        wT[k * OC + oc] = make_float2(v, v);
    }
}

// conv2 weights -> phase-split stride-1 form: k = ch*4 + dy*2 + dx,
// ch = c*4 + py*2 + px, with kh = 2*dy+py, kw = 2*dx+px
__global__ void make_w2ps(const float* __restrict__ w2, float2* __restrict__ wT)
{
    const int i = blockIdx.x * 256 + threadIdx.x;   // over 64*512
    if (i < 64 * 512) {
        const int oc = i / 512, k = i % 512;
        const int ch = k >> 2, dy = (k >> 1) & 1, dx = k & 1;
        const int c = ch >> 2, py = (ch >> 1) & 1, px = ch & 1;
        const int kh = 2 * dy + py, kw = 2 * dx + px;
        const float v = w2[((oc * 32 + c) * 4 + kh) * 4 + kw];
        wT[k * 64 + oc] = make_float2(v, v);
    }
}

// ---------------------------------------------------------------------------
// conv1: patch-gather implicit GEMM (position-paired FFMA2),
// epilogue writes phase-split layout for conv2'.
// ---------------------------------------------------------------------------
template <int C, int H, int W, int K, int S, int OH, int OW, int OC,
          int OCN, int TY, int PP, int NT>
__global__ void __launch_bounds__((OC / OCN) * TY, 2)
conv1_gemm(const float* __restrict__ in, const float2* __restrict__ wT2,
           const float* __restrict__ bias, float* __restrict__ outps)
{
    constexpr int KSQ = K * K, CKK = C * KSQ, TOT = OH * OW;
    constexpr int TX = OC / OCN;
    constexpr int THREADS = TX * TY;
    constexpr int PT = TY * PP * 2;
    constexpr int NPP = PT / THREADS;

    __shared__ float  Ps[16 * PT];
    __shared__ float2 Ws[16 * OC];

    const int tid = threadIdx.x;
    const int tx = tid / TY, ty = tid % TY;

    const int bt = blockIdx.x;
    const int b = bt / NT, tile = bt % NT;
    const int p0 = tile * PT;

    const float* bp[NPP];
#pragma unroll
    for (int j = 0; j < NPP; j++) {
        int pp = p0 + tid + j * THREADS;
        if (pp >= TOT) pp = TOT - 1;
        const int oh = pp / OW, ow = pp % OW;
        bp[j] = in + ((b * C) * H + oh * S) * W + ow * S;
    }

    float bq[OCN];
#pragma unroll
    for (int j = 0; j < OCN; j++) bq[j] = bias[tx * OCN + j];

    u64 acc[PP][OCN];
#pragma unroll
    for (int i = 0; i < PP; i++)
#pragma unroll
        for (int j = 0; j < OCN; j++) acc[i][j] = 0ull;

    for (int kc = 0; kc < CKK; kc += 16) {
        __syncthreads();
#pragma unroll
        for (int e = tid; e < 16 * OC; e += THREADS)
            Ws[e] = wT2[kc * OC + e];
#pragma unroll
        for (int l = 0; l < 16 * NPP; l++) {
            const int kk = l / NPP, j = l % NPP;
            const int k = kc + kk;
            const int c = k / KSQ, r = k - c * KSQ;
            const int kh = r / K, kw = r - kh * K;
            Ps[kk * PT + tid + j * THREADS] = __ldg(bp[j] + (c * H + kh) * W + kw);
        }
        __syncthreads();
#pragma unroll
        for (int kk = 0; kk < 16; kk++) {
            u64 wv[OCN], av[PP];
            const ulonglong2* wp =
                reinterpret_cast<const ulonglong2*>(Ws + kk * OC + tx * OCN);
#pragma unroll
            for (int j = 0; j < OCN / 2; j++) {
                const ulonglong2 t = wp[j];
                wv[2 * j] = t.x; wv[2 * j + 1] = t.y;
            }
            const ulonglong2* pa =
                reinterpret_cast<const ulonglong2*>(Ps + kk * PT + ty * PP * 2);
#pragma unroll
            for (int i = 0; i < PP / 2; i++) {
                const ulonglong2 t = pa[i];
                av[2 * i] = t.x; av[2 * i + 1] = t.y;
            }
#pragma unroll
            for (int i = 0; i < PP; i++)
#pragma unroll
                for (int j = 0; j < OCN; j++)
                    ffma2(acc[i][j], av[i], wv[j]);
        }
    }

    // epilogue: bias + ReLU, scatter to phase-split layout.
    // NOTE: acc[i] holds positions p0 + ty*PP*2 + 2i, +1 (matches compute read).
#pragma unroll
    for (int j = 0; j < OCN; j++) {
        const int oc = tx * OCN + j;
        float* ob = outps + (b * (OC * 4)) * P1S;   // 128 planes base
#pragma unroll
        for (int i = 0; i < PP; i++) {
            float a0, a1;
            unpack2(acc[i][j], a0, a1);
            const int pos = p0 + ty * PP * 2 + 2 * i;
            float v[2] = {fmaxf(a0 + bq[j], 0.f), fmaxf(a1 + bq[j], 0.f)};
#pragma unroll
            for (int e = 0; e < 2; e++) {
                const int p = pos + e;
                if (p < TOT) {
                    const int oh = p / OW, ow = p - oh * OW;
                    const int ch = oc * 4 + (oh & 1) * 2 + (ow & 1);
                    ob[ch * P1S + (oh >> 1) * 28 + (ow >> 1)] = v[e];
                }
            }
        }
    }
}

// ---------------------------------------------------------------------------
// Stride-1 direct conv (conv2' K=2 and conv3 K=3), cp.async double-buffered.
// Thread: OCN ocs x RT rows x 1 width-pair. Input rows staged contiguous;
// per (c,dy,row): two aligned LDS.64 give all K column-pairs.
// ---------------------------------------------------------------------------
template <int C, int IRS, int IPS, int IH, int K, int OW, int OH, int OC,
          int OCN, int TZ, int RT, int CG, int OPS, int OWS>
__global__ void __launch_bounds__((OC / OCN) * (OW / 2) * TZ, 2)
conv_s1(const float* __restrict__ in, const float2* __restrict__ wT2,
        const float* __restrict__ bias, float* __restrict__ out)
{
    constexpr int TYP = OW / 2;
    constexpr int TX = OC / OCN;
    constexpr int THREADS = TX * TYP * TZ;
    constexpr int BR = TZ * RT;
    constexpr int SR = BR + K - 1;
    constexpr int IWP = 28;             // staged row width (=IRS)
    constexpr int KSQ = K * K;
    constexpr int NCH = C / CG;
    constexpr int PSZ = CG * SR * IWP;  // floats per input buffer
    constexpr int WSZ = CG * KSQ * OC;  // float2 per weight buffer
    static_assert(IRS == IWP, "stage full rows");

    extern __shared__ char smraw[];
    float*  Ps = (float*)smraw;                              // 2 * PSZ
    float2* Ws = (float2*)(smraw + 2 * PSZ * sizeof(float)); // 2 * WSZ

    const int tid = threadIdx.x;
    const int tx  = tid / (TYP * TZ);
    const int rem = tid % (TYP * TZ);
    const int tz  = rem / TYP, typ = rem % TYP;

    const int bt = blockIdx.x;
    constexpr int NRB = (OH + BR - 1) / BR;
    const int b = bt / NRB, row0 = (bt % NRB) * BR;

    float bq[OCN];
#pragma unroll
    for (int j = 0; j < OCN; j++) bq[j] = bias[tx * OCN + j];

    u64 acc[RT][OCN];
#pragma unroll
    for (int i = 0; i < RT; i++)
#pragma unroll
        for (int j = 0; j < OCN; j++) acc[i][j] = 0ull;

    auto stage = [&](int buf, int cg0) {
        // input: CG planes x SR rows x IWP cols, clamped rows
        float* Pb = Ps + buf * PSZ;
        constexpr int T4 = PSZ / 4;
        for (int e = tid; e < T4; e += THREADS) {
            const int c = e / (SR * IWP / 4);
            const int r = (e / (IWP / 4)) % SR;
            const int q = e % (IWP / 4);
            int gr = row0 + r; if (gr > IH - 1) gr = IH - 1;
            cp16(su32(Pb + e * 4),
                 in + (b * C + cg0 + c) * IPS + gr * IRS + q * 4);
        }
        // weights: contiguous
        float2* Wb = Ws + buf * WSZ;
        for (int e = tid; e < WSZ / 2; e += THREADS)
            cp16(su32(Wb + e * 2), wT2 + cg0 * KSQ * OC + e * 2);
        cp_commit();
    };

    int buf = 0;
    stage(0, 0);
    for (int ch = 0; ch < NCH; ch++) {
        if (ch + 1 < NCH) { stage(buf ^ 1, (ch + 1) * CG); cp_wait<1>(); }
        else              { cp_wait<0>(); }
        __syncthreads();

        const float*  Pb = Ps + buf * PSZ;
        const float2* Wb = Ws + buf * WSZ;
#pragma unroll 1
        for (int c = 0; c < CG; c++) {
#pragma unroll
            for (int dy = 0; dy < K; dy++) {
                u64 v01[RT], v23[RT];
#pragma unroll
                for (int i = 0; i < RT; i++) {
                    const u64* pp = reinterpret_cast<const u64*>(
                        &Pb[(c * SR + tz * RT + i + dy) * IWP + 2 * typ]);
                    v01[i] = pp[0];
                    v23[i] = pp[1];
                }
#pragma unroll
                for (int dx = 0; dx < K; dx++) {
                    u64 wv[OCN];
                    const ulonglong2* wp = reinterpret_cast<const ulonglong2*>(
                        Wb + (c * KSQ + dy * K + dx) * OC + tx * OCN);
#pragma unroll
                    for (int j = 0; j < OCN / 2; j++) {
                        const ulonglong2 t = wp[j];
                        wv[2 * j] = t.x; wv[2 * j + 1] = t.y;
                    }
#pragma unroll
                    for (int i = 0; i < RT; i++) {
                        u64 a;
                        if (dx == 0)          a = v01[i];
                        else if (dx == K - 1 && K == 3) a = v23[i];
                        else {
                            float x0, x1, y0, y1;
                            unpack2(v01[i], x0, x1);
                            unpack2(v23[i], y0, y1);
                            a = pack2(x1, y0);
                        }
#pragma unroll
                        for (int j = 0; j < OCN; j++)
                            ffma2(acc[i][j], a, wv[j]);
                    }
                }
            }
        }
        __syncthreads();
        buf ^= 1;
    }

    // epilogue: bias + ReLU, float2 stores
#pragma unroll
    for (int j = 0; j < OCN; j++) {
        const int oc = tx * OCN + j;
#pragma unroll
        for (int i = 0; i < RT; i++) {
            const int row = row0 + tz * RT + i;
            if (row < OH) {
                float a0, a1;
                unpack2(acc[i][j], a0, a1);
                *reinterpret_cast<float2*>(
                    out + (b * OC + oc) * OPS + row * OWS + 2 * typ) =
                    make_float2(fmaxf(a0 + bq[j], 0.f), fmaxf(a1 + bq[j], 0.f));
            }
        }
    }
}

// ---------------------------------------------------------------------------
// fc1 split-K GEMM: grid (2,2,145)
// ---------------------------------------------------------------------------
__global__ void fc1_kernel(const float* __restrict__ hist,
                           const float* __restrict__ w1)
{
    __shared__ float As[32 * 68];
    __shared__ float Bs[32 * 68];

    const int m0  = blockIdx.y * 64;
    const int n0  = blockIdx.x * 64;
    const int bz  = blockIdx.z;
    const int tid = threadIdx.x;
    const int ty = tid >> 4, tx = tid & 15;

    float acc[4][4] = {};

    if (bz < NCHUNK - 1) {
        const int kc0 = bz * KCHUNK;
#pragma unroll 1
        for (int kt = 0; kt < KCHUNK; kt += 32) {
            const int kb = kc0 + kt;
#pragma unroll
            for (int l = 0; l < 2; l++) {
                const int idx = tid + l * 256;
                const int row = idx >> 3, kq = idx & 7;
                const float4 v = *reinterpret_cast<const float4*>(
                    g_f3 + (m0 + row) * F3K + kb + kq * 4);
                As[(kq * 4 + 0) * 68 + row] = v.x;
                As[(kq * 4 + 1) * 68 + row] = v.y;
                As[(kq * 4 + 2) * 68 + row] = v.z;
                As[(kq * 4 + 3) * 68 + row] = v.w;
            }
#pragma unroll
            for (int l = 0; l < 4; l++) {
                const int idx = tid + l * 256;
                const int row = idx >> 4, kd = idx & 15;
                const float2 v = *reinterpret_cast<const float2*>(
                    w1 + (n0 + row) * FCK + kb + kd * 2);
                Bs[(kd * 2 + 0) * 68 + row] = v.x;
                Bs[(kd * 2 + 1) * 68 + row] = v.y;
            }
            __syncthreads();
#pragma unroll
            for (int kk = 0; kk < 32; kk++) {
                const float4 a4 = *reinterpret_cast<const float4*>(&As[kk * 68 + ty * 4]);
                const float4 b4 = *reinterpret_cast<const float4*>(&Bs[kk * 68 + tx * 4]);
                const float a[4] = {a4.x, a4.y, a4.z, a4.w};
                const float bb[4] = {b4.x, b4.y, b4.z, b4.w};
#pragma unroll
                for (int i = 0; i < 4; i++)
#pragma unroll
                    for (int j = 0; j < 4; j++)
                        acc[i][j] += a[i] * bb[j];
            }
            __syncthreads();
        }
    } else {
#pragma unroll 1
        for (int kt = 0; kt < 96; kt += 32) {
#pragma unroll
            for (int l = 0; l < 8; l++) {
                const int idx = tid + l * 256;
                const int row = idx >> 5, kk = idx & 31;
                const int k = kt + kk;
                float av = 0.f, bv = 0.f;
                if (k < 90) {
                    av = hist[(m0 + row) * 90 + k];
                    bv = w1[(n0 + row) * FCK + F3K + k];
                }
                As[kk * 68 + row] = av;
                Bs[kk * 68 + row] = bv;
            }
            __syncthreads();
#pragma unroll
            for (int kk = 0; kk < 32; kk++) {
                const float4 a4 = *reinterpret_cast<const float4*>(&As[kk * 68 + ty * 4]);
                const float4 b4 = *reinterpret_cast<const float4*>(&Bs[kk * 68 + tx * 4]);
                const float a[4] = {a4.x, a4.y, a4.z, a4.w};
                const float bb[4] = {b4.x, b4.y, b4.z, b4.w};
#pragma unroll
                for (int i = 0; i < 4; i++)
#pragma unroll
                    for (int j = 0; j < 4; j++)
                        acc[i][j] += a[i] * bb[j];
            }
            __syncthreads();
        }
    }

    float* dst = g_h1p + bz * (BATCH * 128);
#pragma unroll
    for (int i = 0; i < 4; i++)
#pragma unroll
        for (int j = 0; j < 4; j++)
            dst[(m0 + ty * 4 + i) * 128 + (n0 + tx * 4 + j)] = acc[i][j];
}

// ---------------------------------------------------------------------------
// LIF recurrence
// ---------------------------------------------------------------------------
__global__ void lif_kernel(const float* __restrict__ b1,
                           const float* __restrict__ w2,
                           const float* __restrict__ b2,
                           const float* __restrict__ w3,
                           const float* __restrict__ b3,
                           float* __restrict__ out)
{
    extern __shared__ float sm[];
    float* w2s  = sm;
    float* w3s  = w2s + 256 * 129;
    float* spk1 = w3s + 9 * 256;
    float* spk2 = spk1 + 128;

    const int b   = blockIdx.x;
    const int tid = threadIdx.x;

    for (int idx = tid; idx < 256 * 128; idx += blockDim.x) {
        const int j = idx >> 7, i = idx & 127;
        w2s[j * 129 + i] = w2[idx];
    }
    for (int idx = tid; idx < 9 * 256; idx += blockDim.x) w3s[idx] = w3[idx];
    __syncthreads();

    float h1v = 0.f, mem1 = 0.f, syn1 = 0.f;
    if (tid < 128) {
        h1v = b1[tid];
        for (int p = 0; p < NCHUNK; p++)
            h1v += g_h1p[p * (BATCH * 128) + b * 128 + tid];
    }
    float b2v = 0.f, mem2 = 0.f, syn2 = 0.f;
    if (tid < 256) b2v = b2[tid];

    const int w = tid >> 5, lane = tid & 31;
    float b3v = 0.f, mem3 = 0.f, syn3 = 0.f, pot = 0.f;
    if (w < 9 && lane == 0) b3v = b3[w];

    for (int t = 0; t < 10; t++) {
        if (tid < 128) {
            syn1 = 0.9f * syn1 + h1v;
            mem1 = 0.8f * mem1 + syn1;
            const float s = (mem1 > 1.f) ? 1.f : 0.f;
            mem1 -= s;
            spk1[tid] = s;
        }
        __syncthreads();
        if (tid < 256) {
            float h2 = b2v;
#pragma unroll 8
            for (int i = 0; i < 128; i++) h2 += spk1[i] * w2s[tid * 129 + i];
            syn2 = 0.9f * syn2 + h2;
            mem2 = 0.8f * mem2 + syn2;
            const float s = (mem2 > 1.f) ? 1.f : 0.f;
            mem2 -= s;
            spk2[tid] = s;
        }
        __syncthreads();
        if (w < 9) {
            float part = 0.f;
#pragma unroll
            for (int i = 0; i < 8; i++)
                part += spk2[lane + i * 32] * w3s[w * 256 + lane + i * 32];
#pragma unroll
            for (int o = 16; o > 0; o >>= 1)
                part += __shfl_xor_sync(0xffffffff, part, o);
            if (lane == 0) {
                syn3 = 0.9f * syn3 + (part + b3v);
                mem3 = 0.8f * mem3 + syn3;
                pot += mem3;
            }
        }
    }

    if (w < 9 && lane == 0) out[b * 9 + w] = pot * 0.1f;
}

// ---------------------------------------------------------------------------
// Launch
// ---------------------------------------------------------------------------
extern "C" void kernel_launch(void* const* d_in, const int* in_sizes, int n_in,
                              void* d_out, int out_size)
{
    const float* state = (const float*)d_in[0];
    const float* hist  = (const float*)d_in[1];
    const float* cw1   = (const float*)d_in[2];
    const float* cb1   = (const float*)d_in[3];
    const float* cw2   = (const float*)d_in[4];
    const float* cb2   = (const float*)d_in[5];
    const float* cw3   = (const float*)d_in[6];
    const float* cb3   = (const float*)d_in[7];
    const float* w1    = (const float*)d_in[8];
    const float* b1    = (const float*)d_in[9];
    const float* w2    = (const float*)d_in[10];
    const float* b2    = (const float*)d_in[11];
    const float* w3    = (const float*)d_in[12];
    const float* b3    = (const float*)d_in[13];
    float* out = (float*)d_out;

    float*  f1ps; cudaGetSymbolAddress((void**)&f1ps, g_f1ps);
    float*  f2;   cudaGetSymbolAddress((void**)&f2,   g_f2);
    float*  f3;   cudaGetSymbolAddress((void**)&f3,   g_f3);
    float2* wt1;  cudaGetSymbolAddress((void**)&wt1,  g_wt1);
    float2* wt2;  cudaGetSymbolAddress((void**)&wt2,  g_wt2);
    float2* wt3;  cudaGetSymbolAddress((void**)&wt3,  g_wt3);

    transpose_w2<<<(OC1 * 192 + 255) / 256, 256>>>(cw1, wt1, OC1, 192);
    make_w2ps<<<(64 * 512 + 255) / 256, 256>>>(cw2, wt2);
    transpose_w2<<<(OC3 * 576 + 255) / 256, 256>>>(cw3, wt3, OC3, 576);

    // conv1: OCN=8,TY=64,PP=4 -> PT=512, NT=6, 256 thr, grid 768
    conv1_gemm<C1, H1, W1, KK1, S1, OH1, OW1, OC1, 8, 64, 4, 6>
        <<<BATCH * 6, 256>>>(state, wt1, cb1, f1ps);

    // conv2': stride-1 2x2 over 128ch 28x28 -> 64x26x26 (padded rows 28)
    // TX=8, TYP=13, TZ=2 -> 208 thr; RT=4 -> BR=8 -> 4 row-blocks, grid 512
    {
        auto kfn = conv_s1<C2P, 28, P1S, 28, 2, OW2, OH2, OC2, 8, 2, 4, 8, F2PS, F2WS>;
        constexpr int PSZ = 8 * 9 * 28, WSZ = 8 * 4 * OC2;
        const int smem = 2 * PSZ * 4 + 2 * WSZ * 8;   // 48896
        cudaFuncSetAttribute(kfn, cudaFuncAttributeMaxDynamicSharedMemorySize, smem);
        kfn<<<BATCH * 4, 208, smem>>>(f1ps, wt2, cb2, f2);
    }

    // conv3: stride-1 3x3 over 64ch (26 rows, stride-28) -> 64x24x24
    // TX=8, TYP=12, TZ=2 -> 192 thr; RT=4 -> BR=8 -> 3 row-blocks, grid 384
    {
        auto kfn = conv_s1<64, 28, F2PS, 26, 3, OW3, OH3, OC3, 8, 2, 4, 4, TOT3, OW3>;
        constexpr int PSZ = 4 * 10 * 28, WSZ = 4 * 9 * OC3;
        const int smem = 2 * PSZ * 4 + 2 * WSZ * 8;   // 45824
        cudaFuncSetAttribute(kfn, cudaFuncAttributeMaxDynamicSharedMemorySize, smem);
        kfn<<<BATCH * 3, 192, smem>>>(f2, wt3, cb3, f3);
    }

    fc1_kernel<<<dim3(2, 2, NCHUNK), 256>>>(hist, w1);

    const int lif_smem = (256 * 129 + 9 * 256 + 128 + 256) * (int)sizeof(float);
    cudaFuncSetAttribute(lif_kernel, cudaFuncAttributeMaxDynamicSharedMemorySize,
                         lif_smem);
    lif_kernel<<<BATCH, 320, lif_smem>>>(b1, w2, b2, w3, b3, out);
}